// round 7
// baseline (speedup 1.0000x reference)
#include <cuda_runtime.h>
#include <math.h>

#define Bsz 32
#define Rr  256
#define Tt  512
#define Cc  16
#define NC1 64
#define NC2 128

// ---- scratch (static __device__ per allocation rules) ----
__device__ float g_z[67108864];        // [B*C][R][T]  z = (x-mean)*rsqrt(sumsq), 256MB
__device__ float g_y[16777216];        // [B*C][C1][T]  y, 64MB
__device__ float g_epart[4194304];     // [8 cg][32 b][256 r][64 o]
__device__ float g_e[524288];          // [B][R][C1]
__device__ float g_pooled[8192];       // [B][R]
__device__ float g_att[8192];          // [B][R]
__device__ float g_npart[262144];      // [64 splits][32 b][128 j]

__device__ __forceinline__ void fma2(unsigned long long &d,
                                     unsigned long long a,
                                     unsigned long long b) {
    asm("fma.rn.f32x2 %0, %1, %2, %0;" : "+l"(d) : "l"(a), "l"(b));
}
__device__ __forceinline__ unsigned long long packdup(float z) {
    unsigned long long zz;
    unsigned int zi = __float_as_uint(z);
    asm("mov.b64 %0, {%1,%1};" : "=l"(zz) : "r"(zi));
    return zz;
}
__device__ __forceinline__ unsigned long long pack2(float a, float b) {
    unsigned long long r;
    asm("mov.b64 %0, {%1, %2};" : "=l"(r) : "f"(a), "f"(b));
    return r;
}

// ============================================================
// K1: per (b,r): stats + write z[bc][r][t]
// ============================================================
__global__ void k_stats(const float* __restrict__ x) {
    int br = blockIdx.x;                 // b*R + r
    int b = br >> 8, r = br & 255;
    __shared__ __align__(16) float sx[Cc * 513];
    __shared__ float red[256];
    __shared__ float s_mean[Cc], s_inv[Cc];
    const float* xp = x + (size_t)br * (Tt * Cc);
    int tid = threadIdx.x;

    #pragma unroll
    for (int i = 0; i < 8; i++) {
        int idx4 = tid + i * 256;
        int t = idx4 >> 2;
        int c0 = (idx4 & 3) * 4;
        float4 v = *(const float4*)(xp + idx4 * 4);
        sx[(c0 + 0) * 513 + t] = v.x;
        sx[(c0 + 1) * 513 + t] = v.y;
        sx[(c0 + 2) * 513 + t] = v.z;
        sx[(c0 + 3) * 513 + t] = v.w;
    }
    __syncthreads();

    int c = tid & 15, seg = tid >> 4;
    float p = 0.f;
    #pragma unroll
    for (int u = 0; u < 32; u++) p += sx[c * 513 + seg * 32 + u];
    red[seg * 16 + c] = p;
    __syncthreads();
    if (tid < 16) {
        float s = 0.f;
        #pragma unroll
        for (int sg = 0; sg < 16; sg++) s += red[sg * 16 + tid];
        s_mean[tid] = s * (1.0f / Tt);
    }
    __syncthreads();

    float mc = s_mean[c];
    p = 0.f;
    #pragma unroll
    for (int u = 0; u < 32; u++) {
        float d = sx[c * 513 + seg * 32 + u] - mc;
        p += d * d;
    }
    red[seg * 16 + c] = p;
    __syncthreads();
    if (tid < 16) {
        float s = 0.f;
        #pragma unroll
        for (int sg = 0; sg < 16; sg++) s += red[sg * 16 + tid];
        s_inv[tid] = rsqrtf(s);
    }
    __syncthreads();

    int cw = tid >> 4, t0 = tid & 15;
    float m = s_mean[cw], inv = s_inv[cw];
    float* zo = g_z + (((size_t)b * Cc + cw) * Rr + r) * Tt;
    #pragma unroll
    for (int j = 0; j < 32; j++) {
        int t = t0 + j * 16;
        zo[t] = (sx[cw * 513 + t] - m) * inv;
    }
}

// ============================================================
// K2a: y[bc][o][t] = sum_r W_edge[o][c][r] * z[bc][r][t]
// grid 1024 = bc*2 + ttile; block 256; thread tile 8o x 8t.
// W via broadcast LDG (warp-uniform, L1-resident); z via smem.
// ============================================================
__global__ __launch_bounds__(256, 2) void k_y(const float* __restrict__ W_edge) {
    __shared__ __align__(16) float Zs[32 * 260];    // [32 r][260] (t fastest)
    int bc = blockIdx.x >> 1;
    int tt = blockIdx.x & 1;
    int tbase = tt * 256;
    int c = bc & 15;
    int tid = threadIdx.x;
    int og = tid >> 5, lane = tid & 31;
    int o0 = og * 8;
    int ta = lane * 4;
    const float* zb = g_z + (size_t)bc * (Rr * Tt);
    const float* Wc = W_edge + (size_t)c * Rr;   // + o*Cc*Rr + r

    unsigned long long acc2[32];   // [oi 8][q 4]
    #pragma unroll
    for (int i = 0; i < 32; i++) acc2[i] = 0ull;

    for (int kb = 0; kb < 8; kb++) {
        __syncthreads();
        // fill Zs[rl][t] for 32 r x 256 t (direct, coalesced)
        #pragma unroll
        for (int i = 0; i < 8; i++) {
            int idx4 = tid + i * 256;            // 0..2047
            int rl = idx4 >> 6, t4 = idx4 & 63;
            float4 v = *(const float4*)(zb + (size_t)(kb * 32 + rl) * Tt + tbase + t4 * 4);
            *(float4*)(Zs + rl * 260 + t4 * 4) = v;
        }
        __syncthreads();

        #pragma unroll
        for (int kc = 0; kc < 8; kc++) {         // 4-r chunks
            int rb = kb * 32 + kc * 4;
            float4 wq[8];
            #pragma unroll
            for (int oi = 0; oi < 8; oi++)
                wq[oi] = *(const float4*)(Wc + (size_t)(o0 + oi) * (Cc * Rr) + rb);
            #pragma unroll
            for (int kk = 0; kk < 4; kk++) {
                int kl = kc * 4 + kk;
                ulonglong2 zA = *(const ulonglong2*)(Zs + kl * 260 + ta);
                ulonglong2 zB = *(const ulonglong2*)(Zs + kl * 260 + 128 + ta);
                unsigned long long zq0 = zA.x, zq1 = zA.y, zq2 = zB.x, zq3 = zB.y;
                #pragma unroll
                for (int oi = 0; oi < 8; oi++) {
                    float wv = (kk == 0) ? wq[oi].x : (kk == 1) ? wq[oi].y
                             : (kk == 2) ? wq[oi].z : wq[oi].w;
                    unsigned long long wd = packdup(wv);
                    fma2(acc2[oi * 4 + 0], wd, zq0);
                    fma2(acc2[oi * 4 + 1], wd, zq1);
                    fma2(acc2[oi * 4 + 2], wd, zq2);
                    fma2(acc2[oi * 4 + 3], wd, zq3);
                }
            }
        }
    }

    float* yb = g_y + (size_t)bc * (NC1 * Tt);
    #pragma unroll
    for (int oi = 0; oi < 8; oi++) {
        ulonglong2 s0; s0.x = acc2[oi * 4 + 0]; s0.y = acc2[oi * 4 + 1];
        ulonglong2 s1; s1.x = acc2[oi * 4 + 2]; s1.y = acc2[oi * 4 + 3];
        *(ulonglong2*)(yb + (size_t)(o0 + oi) * Tt + tbase + ta) = s0;
        *(ulonglong2*)(yb + (size_t)(o0 + oi) * Tt + tbase + 128 + ta) = s1;
    }
}

// ============================================================
// K2b: epart[cg][b][r][o] = sum_{c in cg} sum_t z[b,c,r,t]*y[b,c,o,t]
// grid 256 = b*8 + cg (2 c's each); block 256; thread tile 8r x 8o.
// y via broadcast LDG; z via XOR-swizzled smem transpose.
//   Zs phys addr(t,r) = t*256 + ((r>>2)^(t>>2))*4 + (r&3)
// ============================================================
__global__ __launch_bounds__(256, 2) void k_e() {
    __shared__ __align__(16) float Zs[32 * 256];    // [t][r] swizzled
    int b = blockIdx.x >> 3;
    int cg = blockIdx.x & 7;
    int tid = threadIdx.x;
    int og = tid >> 5, rg = tid & 31;
    int o0 = og * 8;
    int ra = rg * 4;

    unsigned long long acc2[32];   // [ri 8][op 4]
    #pragma unroll
    for (int i = 0; i < 32; i++) acc2[i] = 0ull;

    for (int ci = 0; ci < 2; ci++) {
        int c = cg * 2 + ci;
        const float* zb = g_z + ((size_t)b * Cc + c) * (Rr * Tt);
        const float* yb = g_y + ((size_t)b * Cc + c) * (NC1 * Tt);
        for (int tc = 0; tc < 16; tc++) {
            __syncthreads();
            // fill Zs[t][r] swizzled (conflict-free scalar stores)
            #pragma unroll
            for (int i = 0; i < 8; i++) {
                int idx4 = tid + i * 256;          // 0..2047
                int r = idx4 >> 3, t4 = idx4 & 7;
                float4 v = *(const float4*)(zb + (size_t)r * Tt + tc * 32 + t4 * 4);
                int q = r >> 2, rm = r & 3;
                Zs[(t4 * 4 + 0) * 256 + ((q ^ t4) << 2) + rm] = v.x;
                Zs[(t4 * 4 + 1) * 256 + ((q ^ t4) << 2) + rm] = v.y;
                Zs[(t4 * 4 + 2) * 256 + ((q ^ t4) << 2) + rm] = v.z;
                Zs[(t4 * 4 + 3) * 256 + ((q ^ t4) << 2) + rm] = v.w;
            }
            __syncthreads();

            #pragma unroll 4
            for (int th = 0; th < 16; th++) {      // 2-t chunks
                float2 yo[8];
                #pragma unroll
                for (int oi = 0; oi < 8; oi++)
                    yo[oi] = *(const float2*)(yb + (size_t)(o0 + oi) * Tt + tc * 32 + th * 2);
                #pragma unroll
                for (int u = 0; u < 2; u++) {
                    int t = th * 2 + u;
                    unsigned long long yp[4];
                    #pragma unroll
                    for (int op = 0; op < 4; op++) {
                        float a0 = (u == 0) ? yo[2 * op].x : yo[2 * op].y;
                        float a1 = (u == 0) ? yo[2 * op + 1].x : yo[2 * op + 1].y;
                        yp[op] = pack2(a0, a1);
                    }
                    int sw = t >> 2;
                    const float* zrow = Zs + t * 256;
                    float4 zAf = *(const float4*)(zrow + ((rg ^ sw) << 2));
                    float4 zBf = *(const float4*)(zrow + ((32 + (rg ^ sw)) << 2));
                    unsigned long long zd[8];
                    zd[0] = packdup(zAf.x); zd[1] = packdup(zAf.y);
                    zd[2] = packdup(zAf.z); zd[3] = packdup(zAf.w);
                    zd[4] = packdup(zBf.x); zd[5] = packdup(zBf.y);
                    zd[6] = packdup(zBf.z); zd[7] = packdup(zBf.w);
                    #pragma unroll
                    for (int ri = 0; ri < 8; ri++) {
                        fma2(acc2[ri * 4 + 0], zd[ri], yp[0]);
                        fma2(acc2[ri * 4 + 1], zd[ri], yp[1]);
                        fma2(acc2[ri * 4 + 2], zd[ri], yp[2]);
                        fma2(acc2[ri * 4 + 3], zd[ri], yp[3]);
                    }
                }
            }
        }
    }

    #pragma unroll
    for (int ri = 0; ri < 8; ri++) {
        int r = (ri < 4) ? (ra + ri) : (128 + ra + ri - 4);
        ulonglong2 s0; s0.x = acc2[ri * 4 + 0]; s0.y = acc2[ri * 4 + 1];
        ulonglong2 s1; s1.x = acc2[ri * 4 + 2]; s1.y = acc2[ri * 4 + 3];
        float* ep = g_epart + (((size_t)cg * Bsz + b) * Rr + r) * NC1 + o0;
        *(ulonglong2*)(ep) = s0;
        *(ulonglong2*)(ep + 4) = s1;
    }
}

// ============================================================
// K3: sum 8 split-K partials, bias + leaky_relu -> e; pooled
// ============================================================
__global__ void k_reduce(const float* __restrict__ b_edge) {
    int br = blockIdx.x;                  // b*R + r
    int b = br >> 8, r = br & 255;
    int o = threadIdx.x;                  // 0..63
    float s = 0.f;
    #pragma unroll
    for (int cg = 0; cg < 8; cg++)
        s += g_epart[(((size_t)cg * Bsz + b) * Rr + r) * NC1 + o];
    s += b_edge[o];
    s = (s > 0.f) ? s : 0.01f * s;
    g_e[((size_t)b * Rr + r) * NC1 + o] = s;

    float v = s;
    #pragma unroll
    for (int off = 16; off > 0; off >>= 1) v += __shfl_down_sync(0xffffffffu, v, off);
    __shared__ float w2[2];
    if ((o & 31) == 0) w2[o >> 5] = v;
    __syncthreads();
    if (o == 0) g_pooled[b * Rr + r] = (w2[0] + w2[1]) * (1.0f / 64.0f);
}

// ============================================================
// K4a: per b: MLP attention (parallelized layer-1).
// ============================================================
__global__ void k_att(const float* __restrict__ W1, const float* __restrict__ b1,
                      const float* __restrict__ W2, const float* __restrict__ b2,
                      float* __restrict__ out) {
    __shared__ __align__(16) float s_p[256];
    __shared__ __align__(16) float s_h[64];
    int b = blockIdx.x, tid = threadIdx.x;

    s_p[tid] = g_pooled[b * Rr + tid];
    __syncthreads();
    {
        int hi = tid >> 2, q = tid & 3;
        const float* w = W1 + hi * 256 + q * 64;
        float a = 0.f;
        #pragma unroll
        for (int j = 0; j < 16; j++) {
            float4 wv = *(const float4*)(w + j * 4);
            float4 pv = *(const float4*)(s_p + q * 64 + j * 4);
            a += wv.x * pv.x + wv.y * pv.y + wv.z * pv.z + wv.w * pv.w;
        }
        a += __shfl_xor_sync(0xffffffffu, a, 1);
        a += __shfl_xor_sync(0xffffffffu, a, 2);
        if (q == 0) {
            a += b1[hi];
            s_h[hi] = a > 0.f ? a : 0.f;
        }
    }
    __syncthreads();
    {
        float a = b2[tid];
        const float* w = W2 + tid * 64;
        #pragma unroll
        for (int j = 0; j < 16; j++) {
            float4 wv = *(const float4*)(w + j * 4);
            float4 hv = *(const float4*)(s_h + j * 4);
            a += wv.x * hv.x + wv.y * hv.y + wv.z * hv.z + wv.w * hv.w;
        }
        float att = 1.0f / (1.0f + expf(-a));
        g_att[b * Rr + tid] = att;
        out[Bsz * NC2 + b * Rr + tid] = att;
    }
}

// ============================================================
// K4b: NodeConv split-K. 64 blocks, each owns 4 r's.
// ============================================================
__global__ __launch_bounds__(256) void k_node(const float* __restrict__ W_node) {
    __shared__ __align__(16) float sae[32 * 256];       // [b][o][rr]
    __shared__ float s_att[128];
    int blk = blockIdx.x;
    int r0 = blk * 4;
    int tid = threadIdx.x;

    if (tid < 128) {
        int b = tid >> 2, rr = tid & 3;
        s_att[tid] = g_att[b * Rr + r0 + rr];
    }
    __syncthreads();

    #pragma unroll
    for (int i = 0; i < 8; i++) {
        int idx4 = tid + i * 256;
        int b = idx4 >> 6, rr = (idx4 >> 4) & 3, o4 = idx4 & 15;
        float4 v = *(const float4*)(g_e + ((size_t)(b * Rr) + r0 + rr) * NC1 + o4 * 4);
        float a = s_att[b * 4 + rr];
        sae[b * 256 + (o4 * 4 + 0) * 4 + rr] = v.x * a;
        sae[b * 256 + (o4 * 4 + 1) * 4 + rr] = v.y * a;
        sae[b * 256 + (o4 * 4 + 2) * 4 + rr] = v.z * a;
        sae[b * 256 + (o4 * 4 + 3) * 4 + rr] = v.w * a;
    }
    __syncthreads();

    int j = tid >> 1, bh = tid & 1;
    unsigned long long acc2[16];
    #pragma unroll
    for (int i = 0; i < 16; i++) acc2[i] = 0ull;

    const float* wj = W_node + (size_t)j * (NC1 * Rr) + r0;
    #pragma unroll 4
    for (int o = 0; o < 64; o++) {
        ulonglong2 w = *(const ulonglong2*)(wj + o * Rr);
        const float* base = sae + bh * 16 * 256 + o * 4;
        #pragma unroll
        for (int bi = 0; bi < 16; bi++) {
            ulonglong2 ae = *(const ulonglong2*)(base + bi * 256);
            fma2(acc2[bi], w.x, ae.x);
            fma2(acc2[bi], w.y, ae.y);
        }
    }

    #pragma unroll
    for (int bi = 0; bi < 16; bi++) {
        float2 p = *(float2*)&acc2[bi];
        int b = bh * 16 + bi;
        g_npart[((size_t)blk * 32 + b) * NC2 + j] = p.x + p.y;
    }
}

// ============================================================
// K4c: reduce 64 split-K partials, bias + leaky_relu -> out
// ============================================================
__global__ void k_nred(const float* __restrict__ b_node, float* __restrict__ out) {
    int b = blockIdx.x, j = threadIdx.x;
    float s = 0.f;
    #pragma unroll 8
    for (int sp = 0; sp < 64; sp++)
        s += g_npart[((size_t)sp * 32 + b) * NC2 + j];
    s += b_node[j];
    out[b * NC2 + j] = s > 0.f ? s : 0.01f * s;
}

// ============================================================
extern "C" void kernel_launch(void* const* d_in, const int* in_sizes, int n_in,
                              void* d_out, int out_size) {
    const float* x      = (const float*)d_in[0];
    const float* W_edge = (const float*)d_in[1];
    const float* b_edge = (const float*)d_in[2];
    const float* W1     = (const float*)d_in[3];
    const float* b1     = (const float*)d_in[4];
    const float* W2     = (const float*)d_in[5];
    const float* b2     = (const float*)d_in[6];
    const float* W_node = (const float*)d_in[7];
    const float* b_node = (const float*)d_in[8];
    float* out = (float*)d_out;

    k_stats <<<Bsz * Rr, 256>>>(x);
    k_y     <<<Bsz * Cc * 2, 256>>>(W_edge);
    k_e     <<<Bsz * 8, 256>>>();
    k_reduce<<<Bsz * Rr, 64>>>(b_edge);
    k_att   <<<Bsz, 256>>>(W1, b1, W2, b2, out);
    k_node  <<<64, 256>>>(W_node);
    k_nred  <<<Bsz, 128>>>(b_node, out);
}

// round 8
// speedup vs baseline: 1.1713x; 1.1713x over previous
#include <cuda_runtime.h>
#include <math.h>

#define Bsz 32
#define Rr  256
#define Tt  512
#define Cc  16
#define NC1 64
#define NC2 128

// ---- scratch (static __device__ per allocation rules) ----
__device__ float g_z[67108864];        // [B*C][R][T]  z, 256MB
__device__ float g_y[16777216];        // [B*C][T][C1]  y TRANSPOSED layout, 64MB
__device__ float g_epart[4194304];     // [8 cg][32 b][256 r][64 o]
__device__ float g_e[524288];          // [B][R][C1]
__device__ float g_pooled[8192];       // [B][R]
__device__ float g_att[8192];          // [B][R]
__device__ float g_npart[262144];      // [64 splits][32 b][128 j]

__device__ __forceinline__ void fma2(unsigned long long &d,
                                     unsigned long long a,
                                     unsigned long long b) {
    asm("fma.rn.f32x2 %0, %1, %2, %0;" : "+l"(d) : "l"(a), "l"(b));
}
__device__ __forceinline__ unsigned long long packdup(float z) {
    unsigned long long zz;
    unsigned int zi = __float_as_uint(z);
    asm("mov.b64 %0, {%1,%1};" : "=l"(zz) : "r"(zi));
    return zz;
}
__device__ __forceinline__ unsigned smem_u32(const void* p) {
    return (unsigned)__cvta_generic_to_shared(p);
}
__device__ __forceinline__ void cp16(unsigned dst, const float* src) {
    asm volatile("cp.async.cg.shared.global [%0], [%1], 16;" :: "r"(dst), "l"(src));
}
#define CP_COMMIT() asm volatile("cp.async.commit_group;")
#define CP_WAIT0()  asm volatile("cp.async.wait_group 0;")

// ============================================================
// K1: per (b,r): stats + write z[bc][r][t]
// ============================================================
__global__ void k_stats(const float* __restrict__ x) {
    int br = blockIdx.x;                 // b*R + r
    int b = br >> 8, r = br & 255;
    __shared__ __align__(16) float sx[Cc * 513];
    __shared__ float red[256];
    __shared__ float s_mean[Cc], s_inv[Cc];
    const float* xp = x + (size_t)br * (Tt * Cc);
    int tid = threadIdx.x;

    #pragma unroll
    for (int i = 0; i < 8; i++) {
        int idx4 = tid + i * 256;
        int t = idx4 >> 2;
        int c0 = (idx4 & 3) * 4;
        float4 v = *(const float4*)(xp + idx4 * 4);
        sx[(c0 + 0) * 513 + t] = v.x;
        sx[(c0 + 1) * 513 + t] = v.y;
        sx[(c0 + 2) * 513 + t] = v.z;
        sx[(c0 + 3) * 513 + t] = v.w;
    }
    __syncthreads();

    int c = tid & 15, seg = tid >> 4;
    float p = 0.f;
    #pragma unroll
    for (int u = 0; u < 32; u++) p += sx[c * 513 + seg * 32 + u];
    red[seg * 16 + c] = p;
    __syncthreads();
    if (tid < 16) {
        float s = 0.f;
        #pragma unroll
        for (int sg = 0; sg < 16; sg++) s += red[sg * 16 + tid];
        s_mean[tid] = s * (1.0f / Tt);
    }
    __syncthreads();

    float mc = s_mean[c];
    p = 0.f;
    #pragma unroll
    for (int u = 0; u < 32; u++) {
        float d = sx[c * 513 + seg * 32 + u] - mc;
        p += d * d;
    }
    red[seg * 16 + c] = p;
    __syncthreads();
    if (tid < 16) {
        float s = 0.f;
        #pragma unroll
        for (int sg = 0; sg < 16; sg++) s += red[sg * 16 + tid];
        s_inv[tid] = rsqrtf(s);
    }
    __syncthreads();

    int cw = tid >> 4, t0 = tid & 15;
    float m = s_mean[cw], inv = s_inv[cw];
    float* zo = g_z + (((size_t)b * Cc + cw) * Rr + r) * Tt;
    #pragma unroll
    for (int j = 0; j < 32; j++) {
        int t = t0 + j * 16;
        zo[t] = (sx[cw * 513 + t] - m) * inv;
    }
}

// ============================================================
// K2a: y[bc][t][o] = sum_r W_edge[o][c][r] * z[bc][r][t]   (y stored [t][o]!)
// grid 1024 = bc*2 + ttile; block 256; thread tile 8o x 8t.
// Double-buffered: Zs via cp.async, Ws via register prefetch.
// smem: Ws[2][32*68] + Zs[2][32*260] = 83,968 B (dynamic)
// ============================================================
__global__ __launch_bounds__(256, 2) void k_y(const float* __restrict__ W_edge) {
    extern __shared__ __align__(16) float smy[];
    float* Ws = smy;                      // [2][32*68]
    float* Zs = smy + 2 * 32 * 68;        // [2][32*260]
    int bc = blockIdx.x >> 1;
    int tt = blockIdx.x & 1;
    int tbase = tt * 256;
    int c = bc & 15;
    int tid = threadIdx.x;
    int og = tid >> 5, lane = tid & 31;
    int o0 = og * 8;
    int ta = lane * 4;
    const float* zb = g_z + (size_t)bc * (Rr * Tt);
    const float* Wc = W_edge + (size_t)c * Rr;

    // per-thread W fill coords: idx4 = tid and tid+256
    int wo0 = tid >> 3, wr4 = tid & 7;
    int wo1 = wo0 + 32;
    float4 wreg0, wreg1;

    // ---- prologue: cp.async Zs chunk 0; LDG Ws chunk 0 ----
    {
        unsigned zdst = smem_u32(Zs);
        #pragma unroll
        for (int i = 0; i < 8; i++) {
            int lin = tid + i * 256;          // 0..2047
            int row = lin >> 6, seg = lin & 63;
            cp16(zdst + (unsigned)(row * 260 + seg * 4) * 4,
                 zb + (size_t)row * Tt + tbase + seg * 4);
        }
        CP_COMMIT();
        wreg0 = *(const float4*)(Wc + (size_t)wo0 * (Cc * Rr) + wr4 * 4);
        wreg1 = *(const float4*)(Wc + (size_t)wo1 * (Cc * Rr) + wr4 * 4);
    }

    unsigned long long acc2[32];   // [oi 8][q 4]
    #pragma unroll
    for (int i = 0; i < 32; i++) acc2[i] = 0ull;

    for (int kb = 0; kb < 8; kb++) {
        float* Wsb = Ws + (kb & 1) * (32 * 68);
        float* Zsb = Zs + (kb & 1) * (32 * 260);
        // STS W regs (transposed) into current buffer
        #pragma unroll
        for (int j = 0; j < 4; j++) {
            float v0 = (j == 0) ? wreg0.x : (j == 1) ? wreg0.y : (j == 2) ? wreg0.z : wreg0.w;
            float v1 = (j == 0) ? wreg1.x : (j == 1) ? wreg1.y : (j == 2) ? wreg1.z : wreg1.w;
            Wsb[(wr4 * 4 + j) * 68 + wo0] = v0;
            Wsb[(wr4 * 4 + j) * 68 + wo1] = v1;
        }
        CP_WAIT0();
        __syncthreads();
        if (kb < 7) {
            float* Zsn = Zs + ((kb + 1) & 1) * (32 * 260);
            unsigned zdst = smem_u32(Zsn);
            #pragma unroll
            for (int i = 0; i < 8; i++) {
                int lin = tid + i * 256;
                int row = lin >> 6, seg = lin & 63;
                cp16(zdst + (unsigned)(row * 260 + seg * 4) * 4,
                     zb + (size_t)((kb + 1) * 32 + row) * Tt + tbase + seg * 4);
            }
            CP_COMMIT();
            wreg0 = *(const float4*)(Wc + (size_t)wo0 * (Cc * Rr) + (kb + 1) * 32 + wr4 * 4);
            wreg1 = *(const float4*)(Wc + (size_t)wo1 * (Cc * Rr) + (kb + 1) * 32 + wr4 * 4);
        }
        // ---- compute (Round-6 inner loop) ----
        #pragma unroll 2
        for (int k = 0; k < 32; k++) {
            float4 wv0 = *(const float4*)(Wsb + k * 68 + o0);
            float4 wv1 = *(const float4*)(Wsb + k * 68 + o0 + 4);
            ulonglong2 zA = *(const ulonglong2*)(Zsb + k * 260 + ta);
            ulonglong2 zB = *(const ulonglong2*)(Zsb + k * 260 + 128 + ta);
            unsigned long long zq0 = zA.x, zq1 = zA.y, zq2 = zB.x, zq3 = zB.y;
            unsigned long long wd[8];
            wd[0] = packdup(wv0.x); wd[1] = packdup(wv0.y);
            wd[2] = packdup(wv0.z); wd[3] = packdup(wv0.w);
            wd[4] = packdup(wv1.x); wd[5] = packdup(wv1.y);
            wd[6] = packdup(wv1.z); wd[7] = packdup(wv1.w);
            #pragma unroll
            for (int oi = 0; oi < 8; oi++) {
                fma2(acc2[oi * 4 + 0], wd[oi], zq0);
                fma2(acc2[oi * 4 + 1], wd[oi], zq1);
                fma2(acc2[oi * 4 + 2], wd[oi], zq2);
                fma2(acc2[oi * 4 + 3], wd[oi], zq3);
            }
        }
    }

    // ---- store y transposed: [bc][t][o] ----
    float* ytb = g_y + (size_t)bc * (Tt * NC1);
    #pragma unroll
    for (int g = 0; g < 2; g++) {
        #pragma unroll
        for (int s = 0; s < 4; s++) {
            int q = g * 2 + (s >> 1);
            int h = s & 1;
            float v[8];
            #pragma unroll
            for (int oi = 0; oi < 8; oi++) {
                float2 p = *(float2*)&acc2[oi * 4 + q];
                v[oi] = h ? p.y : p.x;
            }
            int t = tbase + g * 128 + ta + s;
            *(float4*)(ytb + (size_t)t * NC1 + o0) = make_float4(v[0], v[1], v[2], v[3]);
            *(float4*)(ytb + (size_t)t * NC1 + o0 + 4) = make_float4(v[4], v[5], v[6], v[7]);
        }
    }
}

// ============================================================
// K2b: epart[cg][b][r][o] = sum_{c in cg} sum_t z[b,c,r,t]*y[b,c,t,o]
// grid 256 = b*8 + cg (2 c's each); block 256; thread tile 8r x 8o.
// Double-buffered: Ys via cp.async (y is [t][o] now — direct copy),
// Zs via register prefetch + XOR-swizzled conflict-free transpose:
//   phys(t,r) = t*256 + ((r>>2 ^ t>>2)<<2) + (r&3)
// smem: Zs[2][32*256] + Ys[2][32*64] = 81,920 B (dynamic)
// ============================================================
__global__ __launch_bounds__(256, 2) void k_e() {
    extern __shared__ __align__(16) float sme[];
    float* Zs = sme;                      // [2][32*256]
    float* Ys = sme + 2 * 32 * 256;       // [2][32*64]
    int b = blockIdx.x >> 3;
    int cg = blockIdx.x & 7;
    int tid = threadIdx.x;
    int og = tid >> 5, rg = tid & 31;
    int o0 = og * 8;
    int ra = rg * 4;
    int zr = tid >> 3, zt4 = tid & 7;     // z fill coords

    const float* zb0 = g_z + ((size_t)b * Cc + cg * 2) * (Rr * Tt);
    const float* yb0 = g_y + ((size_t)b * Cc + cg * 2) * (Tt * NC1);

    unsigned long long acc2[32];   // [ri 8][op 4]
    #pragma unroll
    for (int i = 0; i < 32; i++) acc2[i] = 0ull;

    float4 zpre[8];
    // ---- prologue: chunk 0 (ci=0, tc=0) ----
    #pragma unroll
    for (int i = 0; i < 8; i++)
        zpre[i] = *(const float4*)(zb0 + (size_t)(zr + i * 32) * Tt + zt4 * 4);
    {
        unsigned ydst = smem_u32(Ys);
        #pragma unroll
        for (int i = 0; i < 2; i++) {
            int lin = tid + i * 256;          // 0..511
            cp16(ydst + (unsigned)lin * 16, yb0 + lin * 4);
        }
        CP_COMMIT();
    }

    for (int ch = 0; ch < 32; ch++) {
        float* Zsb = Zs + (ch & 1) * (32 * 256);
        float* Ysb = Ys + (ch & 1) * (32 * 64);
        // STS z regs, swizzled (conflict-free)
        #pragma unroll
        for (int i = 0; i < 8; i++) {
            int r = zr + i * 32;
            int base = (((r >> 2) ^ zt4) << 2) + (r & 3);
            float4 v = zpre[i];
            Zsb[(zt4 * 4 + 0) * 256 + base] = v.x;
            Zsb[(zt4 * 4 + 1) * 256 + base] = v.y;
            Zsb[(zt4 * 4 + 2) * 256 + base] = v.z;
            Zsb[(zt4 * 4 + 3) * 256 + base] = v.w;
        }
        CP_WAIT0();
        __syncthreads();
        if (ch < 31) {
            int nch = ch + 1;
            int ci = nch >> 4, tc = nch & 15;
            const float* zb = zb0 + (size_t)ci * (Rr * Tt);
            const float* yb = yb0 + (size_t)ci * (Tt * NC1);
            float* Ysn = Ys + (nch & 1) * (32 * 64);
            unsigned ydst = smem_u32(Ysn);
            #pragma unroll
            for (int i = 0; i < 2; i++) {
                int lin = tid + i * 256;
                cp16(ydst + (unsigned)lin * 16, yb + (size_t)tc * 32 * NC1 + lin * 4);
            }
            CP_COMMIT();
            #pragma unroll
            for (int i = 0; i < 8; i++)
                zpre[i] = *(const float4*)(zb + (size_t)(zr + i * 32) * Tt + tc * 32 + zt4 * 4);
        }
        // ---- compute (Round-6 inner, swizzled z reads, Ys stride 64) ----
        #pragma unroll 4
        for (int t = 0; t < 32; t++) {
            int sw = t >> 2;
            const float* zrow = Zsb + t * 256;
            float4 zAf = *(const float4*)(zrow + ((rg ^ sw) << 2));
            float4 zBf = *(const float4*)(zrow + ((32 + (rg ^ sw)) << 2));
            ulonglong2 yA = *(const ulonglong2*)(Ysb + t * 64 + o0);
            ulonglong2 yB = *(const ulonglong2*)(Ysb + t * 64 + o0 + 4);
            unsigned long long yv0 = yA.x, yv1 = yA.y, yv2 = yB.x, yv3 = yB.y;
            unsigned long long zd[8];
            zd[0] = packdup(zAf.x); zd[1] = packdup(zAf.y);
            zd[2] = packdup(zAf.z); zd[3] = packdup(zAf.w);
            zd[4] = packdup(zBf.x); zd[5] = packdup(zBf.y);
            zd[6] = packdup(zBf.z); zd[7] = packdup(zBf.w);
            #pragma unroll
            for (int ri = 0; ri < 8; ri++) {
                fma2(acc2[ri * 4 + 0], zd[ri], yv0);
                fma2(acc2[ri * 4 + 1], zd[ri], yv1);
                fma2(acc2[ri * 4 + 2], zd[ri], yv2);
                fma2(acc2[ri * 4 + 3], zd[ri], yv3);
            }
        }
    }

    #pragma unroll
    for (int ri = 0; ri < 8; ri++) {
        int r = (ri < 4) ? (ra + ri) : (128 + ra + ri - 4);
        ulonglong2 s0; s0.x = acc2[ri * 4 + 0]; s0.y = acc2[ri * 4 + 1];
        ulonglong2 s1; s1.x = acc2[ri * 4 + 2]; s1.y = acc2[ri * 4 + 3];
        float* ep = g_epart + (((size_t)cg * Bsz + b) * Rr + r) * NC1 + o0;
        *(ulonglong2*)(ep) = s0;
        *(ulonglong2*)(ep + 4) = s1;
    }
}

// ============================================================
// K3: sum 8 split-K partials, bias + leaky_relu -> e; pooled
// ============================================================
__global__ void k_reduce(const float* __restrict__ b_edge) {
    int br = blockIdx.x;                  // b*R + r
    int b = br >> 8, r = br & 255;
    int o = threadIdx.x;                  // 0..63
    float s = 0.f;
    #pragma unroll
    for (int cg = 0; cg < 8; cg++)
        s += g_epart[(((size_t)cg * Bsz + b) * Rr + r) * NC1 + o];
    s += b_edge[o];
    s = (s > 0.f) ? s : 0.01f * s;
    g_e[((size_t)b * Rr + r) * NC1 + o] = s;

    float v = s;
    #pragma unroll
    for (int off = 16; off > 0; off >>= 1) v += __shfl_down_sync(0xffffffffu, v, off);
    __shared__ float w2[2];
    if ((o & 31) == 0) w2[o >> 5] = v;
    __syncthreads();
    if (o == 0) g_pooled[b * Rr + r] = (w2[0] + w2[1]) * (1.0f / 64.0f);
}

// ============================================================
// K4a: per b: MLP attention (parallelized layer-1).
// ============================================================
__global__ void k_att(const float* __restrict__ W1, const float* __restrict__ b1,
                      const float* __restrict__ W2, const float* __restrict__ b2,
                      float* __restrict__ out) {
    __shared__ __align__(16) float s_p[256];
    __shared__ __align__(16) float s_h[64];
    int b = blockIdx.x, tid = threadIdx.x;

    s_p[tid] = g_pooled[b * Rr + tid];
    __syncthreads();
    {
        int hi = tid >> 2, q = tid & 3;
        const float* w = W1 + hi * 256 + q * 64;
        float a = 0.f;
        #pragma unroll
        for (int j = 0; j < 16; j++) {
            float4 wv = *(const float4*)(w + j * 4);
            float4 pv = *(const float4*)(s_p + q * 64 + j * 4);
            a += wv.x * pv.x + wv.y * pv.y + wv.z * pv.z + wv.w * pv.w;
        }
        a += __shfl_xor_sync(0xffffffffu, a, 1);
        a += __shfl_xor_sync(0xffffffffu, a, 2);
        if (q == 0) {
            a += b1[hi];
            s_h[hi] = a > 0.f ? a : 0.f;
        }
    }
    __syncthreads();
    {
        float a = b2[tid];
        const float* w = W2 + tid * 64;
        #pragma unroll
        for (int j = 0; j < 16; j++) {
            float4 wv = *(const float4*)(w + j * 4);
            float4 hv = *(const float4*)(s_h + j * 4);
            a += wv.x * hv.x + wv.y * hv.y + wv.z * hv.z + wv.w * hv.w;
        }
        float att = 1.0f / (1.0f + expf(-a));
        g_att[b * Rr + tid] = att;
        out[Bsz * NC2 + b * Rr + tid] = att;
    }
}

// ============================================================
// K4b: NodeConv split-K. 64 blocks, each owns 4 r's.
// ============================================================
__global__ __launch_bounds__(256) void k_node(const float* __restrict__ W_node) {
    __shared__ __align__(16) float sae[32 * 256];       // [b][o][rr]
    __shared__ float s_att[128];
    int blk = blockIdx.x;
    int r0 = blk * 4;
    int tid = threadIdx.x;

    if (tid < 128) {
        int b = tid >> 2, rr = tid & 3;
        s_att[tid] = g_att[b * Rr + r0 + rr];
    }
    __syncthreads();

    #pragma unroll
    for (int i = 0; i < 8; i++) {
        int idx4 = tid + i * 256;
        int b = idx4 >> 6, rr = (idx4 >> 4) & 3, o4 = idx4 & 15;
        float4 v = *(const float4*)(g_e + ((size_t)(b * Rr) + r0 + rr) * NC1 + o4 * 4);
        float a = s_att[b * 4 + rr];
        sae[b * 256 + (o4 * 4 + 0) * 4 + rr] = v.x * a;
        sae[b * 256 + (o4 * 4 + 1) * 4 + rr] = v.y * a;
        sae[b * 256 + (o4 * 4 + 2) * 4 + rr] = v.z * a;
        sae[b * 256 + (o4 * 4 + 3) * 4 + rr] = v.w * a;
    }
    __syncthreads();

    int j = tid >> 1, bh = tid & 1;
    unsigned long long acc2[16];
    #pragma unroll
    for (int i = 0; i < 16; i++) acc2[i] = 0ull;

    const float* wj = W_node + (size_t)j * (NC1 * Rr) + r0;
    #pragma unroll 4
    for (int o = 0; o < 64; o++) {
        ulonglong2 w = *(const ulonglong2*)(wj + o * Rr);
        const float* base = sae + bh * 16 * 256 + o * 4;
        #pragma unroll
        for (int bi = 0; bi < 16; bi++) {
            ulonglong2 ae = *(const ulonglong2*)(base + bi * 256);
            fma2(acc2[bi], w.x, ae.x);
            fma2(acc2[bi], w.y, ae.y);
        }
    }

    #pragma unroll
    for (int bi = 0; bi < 16; bi++) {
        float2 p = *(float2*)&acc2[bi];
        int b = bh * 16 + bi;
        g_npart[((size_t)blk * 32 + b) * NC2 + j] = p.x + p.y;
    }
}

// ============================================================
// K4c: reduce 64 split-K partials, bias + leaky_relu -> out
// ============================================================
__global__ void k_nred(const float* __restrict__ b_node, float* __restrict__ out) {
    int b = blockIdx.x, j = threadIdx.x;
    float s = 0.f;
    #pragma unroll 8
    for (int sp = 0; sp < 64; sp++)
        s += g_npart[((size_t)sp * 32 + b) * NC2 + j];
    s += b_node[j];
    out[b * NC2 + j] = s > 0.f ? s : 0.01f * s;
}

// ============================================================
extern "C" void kernel_launch(void* const* d_in, const int* in_sizes, int n_in,
                              void* d_out, int out_size) {
    const float* x      = (const float*)d_in[0];
    const float* W_edge = (const float*)d_in[1];
    const float* b_edge = (const float*)d_in[2];
    const float* W1     = (const float*)d_in[3];
    const float* b1     = (const float*)d_in[4];
    const float* W2     = (const float*)d_in[5];
    const float* b2     = (const float*)d_in[6];
    const float* W_node = (const float*)d_in[7];
    const float* b_node = (const float*)d_in[8];
    float* out = (float*)d_out;

    const int smemY = (2 * 32 * 68 + 2 * 32 * 260) * 4;   // 83,968 B
    const int smemE = (2 * 32 * 256 + 2 * 32 * 64) * 4;   // 81,920 B
    cudaFuncSetAttribute(k_y, cudaFuncAttributeMaxDynamicSharedMemorySize, smemY);
    cudaFuncSetAttribute(k_e, cudaFuncAttributeMaxDynamicSharedMemorySize, smemE);

    k_stats <<<Bsz * Rr, 256>>>(x);
    k_y     <<<Bsz * Cc * 2, 256, smemY>>>(W_edge);
    k_e     <<<Bsz * 8, 256, smemE>>>();
    k_reduce<<<Bsz * Rr, 64>>>(b_edge);
    k_att   <<<Bsz, 256>>>(W1, b1, W2, b2, out);
    k_node  <<<64, 256>>>(W_node);
    k_nred  <<<Bsz, 128>>>(b_node, out);
}

// round 10
// speedup vs baseline: 1.3144x; 1.1222x over previous
#include <cuda_runtime.h>
#include <cuda_bf16.h>
#include <math.h>

#define Bsz 32
#define Rr  256
#define Tt  512
#define Cc  16
#define NC1 64
#define NC2 128

// ---- scratch (static __device__ per allocation rules) ----
__device__ float g_z[67108864];                 // [B*C][R][T] fp32 z (for k_y), 256MB
__device__ __nv_bfloat16 g_zh[67108864];        // bf16 hi of z
__device__ __nv_bfloat16 g_zl[67108864];        // bf16 lo of z
__device__ __nv_bfloat16 g_yh[16777216];        // [B*C][C1][T] bf16 hi of y
__device__ __nv_bfloat16 g_yl[16777216];        // bf16 lo of y
__device__ float g_epart[2097152];              // [4 cg][32 b][256 r][64 o]
__device__ float g_e[524288];                   // [B][R][C1]
__device__ float g_pooled[8192];                // [B][R]
__device__ float g_att[8192];                   // [B][R]
__device__ float g_npart[262144];               // [64 splits][32 b][128 j]

__device__ __forceinline__ void fma2(unsigned long long &d,
                                     unsigned long long a,
                                     unsigned long long b) {
    asm("fma.rn.f32x2 %0, %1, %2, %0;" : "+l"(d) : "l"(a), "l"(b));
}
__device__ __forceinline__ unsigned long long packdup(float z) {
    unsigned long long zz;
    unsigned int zi = __float_as_uint(z);
    asm("mov.b64 %0, {%1,%1};" : "=l"(zz) : "r"(zi));
    return zz;
}
__device__ __forceinline__ unsigned smem_u32(const void* p) {
    return (unsigned)__cvta_generic_to_shared(p);
}
__device__ __forceinline__ void cp16(unsigned dst, const void* src) {
    asm volatile("cp.async.cg.shared.global [%0], [%1], 16;" :: "r"(dst), "l"(src));
}
#define CP_COMMIT() asm volatile("cp.async.commit_group;")
#define CP_WAIT0()  asm volatile("cp.async.wait_group 0;")
#define CP_WAIT1()  asm volatile("cp.async.wait_group 1;")

// bf16 2-way split of a float pair. hi word: [lo16]=bf16(a), [hi16]=bf16(b).
__device__ __forceinline__ void bf16_split2(float a, float b, unsigned &hi, unsigned &lo) {
    unsigned h;
    asm("cvt.rn.bf16x2.f32 %0, %1, %2;" : "=r"(h) : "f"(b), "f"(a));
    float ha = __uint_as_float(h << 16);
    float hb = __uint_as_float(h & 0xffff0000u);
    unsigned l;
    asm("cvt.rn.bf16x2.f32 %0, %1, %2;" : "=r"(l) : "f"(b - hb), "f"(a - ha));
    hi = h; lo = l;
}

// ---- warp-level tensor core (sm_80+ baseline; works on compute_103) ----
#define LDSM4(r, addr) \
    asm volatile("ldmatrix.sync.aligned.m8n8.x4.shared.b16 {%0,%1,%2,%3}, [%4];" \
        : "=r"((r)[0]), "=r"((r)[1]), "=r"((r)[2]), "=r"((r)[3]) : "r"(addr))

#define MMA16816(d, a, bp) \
    asm volatile("mma.sync.aligned.m16n8k16.row.col.f32.bf16.bf16.f32 " \
        "{%0,%1,%2,%3}, {%4,%5,%6,%7}, {%8,%9}, {%0,%1,%2,%3};" \
        : "+f"((d)[0]), "+f"((d)[1]), "+f"((d)[2]), "+f"((d)[3]) \
        : "r"((a)[0]), "r"((a)[1]), "r"((a)[2]), "r"((a)[3]), \
          "r"((bp)[0]), "r"((bp)[1]))

// ============================================================
// K1: per (b,r): stats + write z fp32 [bc][r][t] + bf16 hi/lo split
// ============================================================
__global__ void k_stats(const float* __restrict__ x) {
    int br = blockIdx.x;                 // b*R + r
    int b = br >> 8, r = br & 255;
    __shared__ __align__(16) float sx[Cc * 513];
    __shared__ float red[256];
    __shared__ float s_mean[Cc], s_inv[Cc];
    const float* xp = x + (size_t)br * (Tt * Cc);
    int tid = threadIdx.x;

    #pragma unroll
    for (int i = 0; i < 8; i++) {
        int idx4 = tid + i * 256;
        int t = idx4 >> 2;
        int c0 = (idx4 & 3) * 4;
        float4 v = *(const float4*)(xp + idx4 * 4);
        sx[(c0 + 0) * 513 + t] = v.x;
        sx[(c0 + 1) * 513 + t] = v.y;
        sx[(c0 + 2) * 513 + t] = v.z;
        sx[(c0 + 3) * 513 + t] = v.w;
    }
    __syncthreads();

    int c = tid & 15, seg = tid >> 4;
    float p = 0.f;
    #pragma unroll
    for (int u = 0; u < 32; u++) p += sx[c * 513 + seg * 32 + u];
    red[seg * 16 + c] = p;
    __syncthreads();
    if (tid < 16) {
        float s = 0.f;
        #pragma unroll
        for (int sg = 0; sg < 16; sg++) s += red[sg * 16 + tid];
        s_mean[tid] = s * (1.0f / Tt);
    }
    __syncthreads();

    float mc = s_mean[c];
    p = 0.f;
    #pragma unroll
    for (int u = 0; u < 32; u++) {
        float d = sx[c * 513 + seg * 32 + u] - mc;
        p += d * d;
    }
    red[seg * 16 + c] = p;
    __syncthreads();
    if (tid < 16) {
        float s = 0.f;
        #pragma unroll
        for (int sg = 0; sg < 16; sg++) s += red[sg * 16 + tid];
        s_inv[tid] = rsqrtf(s);
    }
    __syncthreads();

    int cw = tid >> 4, t0 = tid & 15;
    float m = s_mean[cw], inv = s_inv[cw];
    size_t zoff = (((size_t)b * Cc + cw) * Rr + r) * Tt;
    float* zo = g_z + zoff;
    #pragma unroll
    for (int j = 0; j < 32; j++) {
        int t = t0 + j * 16;
        zo[t] = (sx[cw * 513 + t] - m) * inv;
    }
    __nv_bfloat16* zh = g_zh + zoff;
    __nv_bfloat16* zl = g_zl + zoff;
    int q = tid & 15;
    #pragma unroll
    for (int j = 0; j < 16; j++) {
        int t = q * 2 + j * 32;
        float z0 = (sx[cw * 513 + t] - m) * inv;
        float z1 = (sx[cw * 513 + t + 1] - m) * inv;
        unsigned hw, lw;
        bf16_split2(z0, z1, hw, lw);
        *(unsigned*)(zh + t) = hw;
        *(unsigned*)(zl + t) = lw;
    }
}

// ============================================================
// K2a: y[bc][o][t] = sum_r W_edge[o][c][r] * z[bc][r][t]
// grid 1024; block 256; thread tile 8o x 8t; double-buffered (R8).
// Epilogue stores bf16 hi/lo y in [o][t].
// ============================================================
__global__ __launch_bounds__(256, 2) void k_y(const float* __restrict__ W_edge) {
    extern __shared__ __align__(16) float smy[];
    float* Ws = smy;                      // [2][32*68]
    float* Zs = smy + 2 * 32 * 68;        // [2][32*260]
    int bc = blockIdx.x >> 1;
    int tt = blockIdx.x & 1;
    int tbase = tt * 256;
    int c = bc & 15;
    int tid = threadIdx.x;
    int og = tid >> 5, lane = tid & 31;
    int o0 = og * 8;
    int ta = lane * 4;
    const float* zb = g_z + (size_t)bc * (Rr * Tt);
    const float* Wc = W_edge + (size_t)c * Rr;

    int wo0 = tid >> 3, wr4 = tid & 7;
    int wo1 = wo0 + 32;
    float4 wreg0, wreg1;

    {
        unsigned zdst = smem_u32(Zs);
        #pragma unroll
        for (int i = 0; i < 8; i++) {
            int lin = tid + i * 256;
            int row = lin >> 6, seg = lin & 63;
            cp16(zdst + (unsigned)(row * 260 + seg * 4) * 4,
                 zb + (size_t)row * Tt + tbase + seg * 4);
        }
        CP_COMMIT();
        wreg0 = *(const float4*)(Wc + (size_t)wo0 * (Cc * Rr) + wr4 * 4);
        wreg1 = *(const float4*)(Wc + (size_t)wo1 * (Cc * Rr) + wr4 * 4);
    }

    unsigned long long acc2[32];
    #pragma unroll
    for (int i = 0; i < 32; i++) acc2[i] = 0ull;

    for (int kb = 0; kb < 8; kb++) {
        float* Wsb = Ws + (kb & 1) * (32 * 68);
        float* Zsb = Zs + (kb & 1) * (32 * 260);
        #pragma unroll
        for (int j = 0; j < 4; j++) {
            float v0 = (j == 0) ? wreg0.x : (j == 1) ? wreg0.y : (j == 2) ? wreg0.z : wreg0.w;
            float v1 = (j == 0) ? wreg1.x : (j == 1) ? wreg1.y : (j == 2) ? wreg1.z : wreg1.w;
            Wsb[(wr4 * 4 + j) * 68 + wo0] = v0;
            Wsb[(wr4 * 4 + j) * 68 + wo1] = v1;
        }
        CP_WAIT0();
        __syncthreads();
        if (kb < 7) {
            float* Zsn = Zs + ((kb + 1) & 1) * (32 * 260);
            unsigned zdst = smem_u32(Zsn);
            #pragma unroll
            for (int i = 0; i < 8; i++) {
                int lin = tid + i * 256;
                int row = lin >> 6, seg = lin & 63;
                cp16(zdst + (unsigned)(row * 260 + seg * 4) * 4,
                     zb + (size_t)((kb + 1) * 32 + row) * Tt + tbase + seg * 4);
            }
            CP_COMMIT();
            wreg0 = *(const float4*)(Wc + (size_t)wo0 * (Cc * Rr) + (kb + 1) * 32 + wr4 * 4);
            wreg1 = *(const float4*)(Wc + (size_t)wo1 * (Cc * Rr) + (kb + 1) * 32 + wr4 * 4);
        }
        #pragma unroll 2
        for (int k = 0; k < 32; k++) {
            float4 wv0 = *(const float4*)(Wsb + k * 68 + o0);
            float4 wv1 = *(const float4*)(Wsb + k * 68 + o0 + 4);
            ulonglong2 zA = *(const ulonglong2*)(Zsb + k * 260 + ta);
            ulonglong2 zB = *(const ulonglong2*)(Zsb + k * 260 + 128 + ta);
            unsigned long long zq0 = zA.x, zq1 = zA.y, zq2 = zB.x, zq3 = zB.y;
            unsigned long long wd[8];
            wd[0] = packdup(wv0.x); wd[1] = packdup(wv0.y);
            wd[2] = packdup(wv0.z); wd[3] = packdup(wv0.w);
            wd[4] = packdup(wv1.x); wd[5] = packdup(wv1.y);
            wd[6] = packdup(wv1.z); wd[7] = packdup(wv1.w);
            #pragma unroll
            for (int oi = 0; oi < 8; oi++) {
                fma2(acc2[oi * 4 + 0], wd[oi], zq0);
                fma2(acc2[oi * 4 + 1], wd[oi], zq1);
                fma2(acc2[oi * 4 + 2], wd[oi], zq2);
                fma2(acc2[oi * 4 + 3], wd[oi], zq3);
            }
        }
    }

    // ---- epilogue: split to bf16 hi/lo, store y [bc][o][t] ----
    __nv_bfloat16* yhb = g_yh + (size_t)bc * (NC1 * Tt);
    __nv_bfloat16* ylb = g_yl + (size_t)bc * (NC1 * Tt);
    #pragma unroll
    for (int oi = 0; oi < 8; oi++) {
        size_t row = (size_t)(o0 + oi) * Tt + tbase;
        #pragma unroll
        for (int h = 0; h < 2; h++) {
            float2 pA = *(float2*)&acc2[oi * 4 + h * 2 + 0];
            float2 pB = *(float2*)&acc2[oi * 4 + h * 2 + 1];
            unsigned h0, l0, h1, l1;
            bf16_split2(pA.x, pA.y, h0, l0);
            bf16_split2(pB.x, pB.y, h1, l1);
            uint2 hv; hv.x = h0; hv.y = h1;
            uint2 lv; lv.x = l0; lv.y = l1;
            *(uint2*)(yhb + row + h * 128 + ta) = hv;
            *(uint2*)(ylb + row + h * 128 + ta) = lv;
        }
    }
}

// ============================================================
// K2b (HMMA): epart[cq][b][r][o] = sum_{c in cq-group} sum_t z·y
// grid 128 = b*4 + cq (4 c's each); block 256 (8 warps).
// A = zh/zl [256 r][32 t] bf16 rows padded to 40 elems (80B);
// B = yh/yl [64 o][32 t]  same padding. ldmatrix non-trans both.
// 3 chains: hh + hl + lh. Warp tile 32r x 64o.
// 2-stage cp.async pipeline; stage = 51,200 B.
// ============================================================
#define AH_OFF 0
#define AL_OFF 20480
#define BH_OFF 40960
#define BL_OFF 46080
#define EST    51200

__global__ __launch_bounds__(256, 1) void k_e_hmma() {
    extern __shared__ __align__(16) char esm[];
    unsigned base = smem_u32(esm);
    int tid = threadIdx.x;
    int wid = tid >> 5, lane = tid & 31;
    int b = blockIdx.x >> 2, cq = blockIdx.x & 3;

    const __nv_bfloat16* zh0 = g_zh + (size_t)(b * Cc + cq * 4) * Rr * Tt;
    const __nv_bfloat16* zl0 = g_zl + (size_t)(b * Cc + cq * 4) * Rr * Tt;
    const __nv_bfloat16* yh0 = g_yh + (size_t)(b * Cc + cq * 4) * NC1 * Tt;
    const __nv_bfloat16* yl0 = g_yl + (size_t)(b * Cc + cq * 4) * NC1 * Tt;

    int brow = tid & 63, bj = tid >> 6;

    auto fill = [&](int ch, unsigned stage) {
        int ci = ch >> 4, tcn = ch & 15;
        const __nv_bfloat16* zh = zh0 + (size_t)ci * Rr * Tt + tcn * 32;
        const __nv_bfloat16* zl = zl0 + (size_t)ci * Rr * Tt + tcn * 32;
        const __nv_bfloat16* yh = yh0 + (size_t)ci * NC1 * Tt + tcn * 32;
        const __nv_bfloat16* yl = yl0 + (size_t)ci * NC1 * Tt + tcn * 32;
        int r = tid;
        #pragma unroll
        for (int j = 0; j < 4; j++) {
            cp16(stage + AH_OFF + (unsigned)(r * 80 + j * 16), zh + (size_t)r * Tt + j * 8);
            cp16(stage + AL_OFF + (unsigned)(r * 80 + j * 16), zl + (size_t)r * Tt + j * 8);
        }
        cp16(stage + BH_OFF + (unsigned)(brow * 80 + bj * 16), yh + (size_t)brow * Tt + bj * 8);
        cp16(stage + BL_OFF + (unsigned)(brow * 80 + bj * 16), yl + (size_t)brow * Tt + bj * 8);
        CP_COMMIT();
    };

    float acc[2][8][4];
    #pragma unroll
    for (int mt = 0; mt < 2; mt++)
        #pragma unroll
        for (int nt = 0; nt < 8; nt++)
            #pragma unroll
            for (int u = 0; u < 4; u++) acc[mt][nt][u] = 0.f;

    // ldmatrix per-lane row addressing
    int matq = lane >> 3, qr = lane & 7;
    unsigned a_row = (unsigned)(((matq & 1) * 8 + qr) * 80 + (matq >> 1) * 16);   // within m16 tile
    unsigned b_row = (unsigned)((((matq >> 1) * 8 + qr)) * 80 + (matq & 1) * 16); // within n16 pair

    fill(0, base);
    for (int ch = 0; ch < 64; ch++) {
        unsigned s = base + (unsigned)(ch & 1) * EST;
        __syncthreads();
        if (ch + 1 < 64) {
            fill(ch + 1, base + (unsigned)((ch + 1) & 1) * EST);
            CP_WAIT1();
        } else {
            CP_WAIT0();
        }
        __syncthreads();

        unsigned Ah = s + AH_OFF + (unsigned)(wid * 32) * 80 + a_row;
        unsigned Al = s + AL_OFF + (unsigned)(wid * 32) * 80 + a_row;
        unsigned Bh = s + BH_OFF + b_row;
        unsigned Bl = s + BL_OFF + b_row;

        #pragma unroll
        for (int k0 = 0; k0 < 2; k0++) {
            unsigned koff = (unsigned)(k0 * 32);   // 16 elems * 2B
            unsigned ah[2][4], al[2][4];
            LDSM4(ah[0], Ah + koff);
            LDSM4(ah[1], Ah + 16 * 80 + koff);
            LDSM4(al[0], Al + koff);
            LDSM4(al[1], Al + 16 * 80 + koff);
            unsigned bh[4][4], bl[4][4];
            #pragma unroll
            for (int i = 0; i < 4; i++) {
                LDSM4(bh[i], Bh + (unsigned)(i * 16) * 80 + koff);
                LDSM4(bl[i], Bl + (unsigned)(i * 16) * 80 + koff);
            }
            #pragma unroll
            for (int mt = 0; mt < 2; mt++) {
                #pragma unroll
                for (int i = 0; i < 4; i++) {
                    #pragma unroll
                    for (int h = 0; h < 2; h++) {
                        int nt = i * 2 + h;
                        MMA16816(acc[mt][nt], ah[mt], &bh[i][h * 2]);
                        MMA16816(acc[mt][nt], ah[mt], &bl[i][h * 2]);
                        MMA16816(acc[mt][nt], al[mt], &bh[i][h * 2]);
                    }
                }
            }
        }
    }

    // epilogue: write split-K partials
    int g = lane >> 2, tc = lane & 3;
    float* ep = g_epart + ((size_t)cq * Bsz + b) * Rr * NC1;
    #pragma unroll
    for (int mt = 0; mt < 2; mt++) {
        #pragma unroll
        for (int nt = 0; nt < 8; nt++) {
            int r = wid * 32 + mt * 16 + g;
            int o = nt * 8 + tc * 2;
            *(float2*)(ep + (size_t)r * NC1 + o) = make_float2(acc[mt][nt][0], acc[mt][nt][1]);
            *(float2*)(ep + (size_t)(r + 8) * NC1 + o) = make_float2(acc[mt][nt][2], acc[mt][nt][3]);
        }
    }
}

// ============================================================
// K3: sum 4 split-K partials, bias + leaky_relu -> e; pooled
// ============================================================
__global__ void k_reduce(const float* __restrict__ b_edge) {
    int br = blockIdx.x;                  // b*R + r
    int b = br >> 8, r = br & 255;
    int o = threadIdx.x;                  // 0..63
    float s = 0.f;
    #pragma unroll
    for (int cg = 0; cg < 4; cg++)
        s += g_epart[(((size_t)cg * Bsz + b) * Rr + r) * NC1 + o];
    s += b_edge[o];
    s = (s > 0.f) ? s : 0.01f * s;
    g_e[((size_t)b * Rr + r) * NC1 + o] = s;

    float v = s;
    #pragma unroll
    for (int off = 16; off > 0; off >>= 1) v += __shfl_down_sync(0xffffffffu, v, off);
    __shared__ float w2[2];
    if ((o & 31) == 0) w2[o >> 5] = v;
    __syncthreads();
    if (o == 0) g_pooled[b * Rr + r] = (w2[0] + w2[1]) * (1.0f / 64.0f);
}

// ============================================================
// K4a: per b: MLP attention (parallelized layer-1).
// ============================================================
__global__ void k_att(const float* __restrict__ W1, const float* __restrict__ b1,
                      const float* __restrict__ W2, const float* __restrict__ b2,
                      float* __restrict__ out) {
    __shared__ __align__(16) float s_p[256];
    __shared__ __align__(16) float s_h[64];
    int b = blockIdx.x, tid = threadIdx.x;

    s_p[tid] = g_pooled[b * Rr + tid];
    __syncthreads();
    {
        int hi = tid >> 2, q = tid & 3;
        const float* w = W1 + hi * 256 + q * 64;
        float a = 0.f;
        #pragma unroll
        for (int j = 0; j < 16; j++) {
            float4 wv = *(const float4*)(w + j * 4);
            float4 pv = *(const float4*)(s_p + q * 64 + j * 4);
            a += wv.x * pv.x + wv.y * pv.y + wv.z * pv.z + wv.w * pv.w;
        }
        a += __shfl_xor_sync(0xffffffffu, a, 1);
        a += __shfl_xor_sync(0xffffffffu, a, 2);
        if (q == 0) {
            a += b1[hi];
            s_h[hi] = a > 0.f ? a : 0.f;
        }
    }
    __syncthreads();
    {
        float a = b2[tid];
        const float* w = W2 + tid * 64;
        #pragma unroll
        for (int j = 0; j < 16; j++) {
            float4 wv = *(const float4*)(w + j * 4);
            float4 hv = *(const float4*)(s_h + j * 4);
            a += wv.x * hv.x + wv.y * hv.y + wv.z * hv.z + wv.w * hv.w;
        }
        float att = 1.0f / (1.0f + expf(-a));
        g_att[b * Rr + tid] = att;
        out[Bsz * NC2 + b * Rr + tid] = att;
    }
}

// ============================================================
// K4b: NodeConv split-K. 64 blocks, each owns 4 r's.
// ============================================================
__global__ __launch_bounds__(256) void k_node(const float* __restrict__ W_node) {
    __shared__ __align__(16) float sae[32 * 256];       // [b][o][rr]
    __shared__ float s_att[128];
    int blk = blockIdx.x;
    int r0 = blk * 4;
    int tid = threadIdx.x;

    if (tid < 128) {
        int b = tid >> 2, rr = tid & 3;
        s_att[tid] = g_att[b * Rr + r0 + rr];
    }
    __syncthreads();

    #pragma unroll
    for (int i = 0; i < 8; i++) {
        int idx4 = tid + i * 256;
        int b = idx4 >> 6, rr = (idx4 >> 4) & 3, o4 = idx4 & 15;
        float4 v = *(const float4*)(g_e + ((size_t)(b * Rr) + r0 + rr) * NC1 + o4 * 4);
        float a = s_att[b * 4 + rr];
        sae[b * 256 + (o4 * 4 + 0) * 4 + rr] = v.x * a;
        sae[b * 256 + (o4 * 4 + 1) * 4 + rr] = v.y * a;
        sae[b * 256 + (o4 * 4 + 2) * 4 + rr] = v.z * a;
        sae[b * 256 + (o4 * 4 + 3) * 4 + rr] = v.w * a;
    }
    __syncthreads();

    int j = tid >> 1, bh = tid & 1;
    unsigned long long acc2[16];
    #pragma unroll
    for (int i = 0; i < 16; i++) acc2[i] = 0ull;

    const float* wj = W_node + (size_t)j * (NC1 * Rr) + r0;
    #pragma unroll 4
    for (int o = 0; o < 64; o++) {
        ulonglong2 w = *(const ulonglong2*)(wj + o * Rr);
        const float* bsp = sae + bh * 16 * 256 + o * 4;
        #pragma unroll
        for (int bi = 0; bi < 16; bi++) {
            ulonglong2 ae = *(const ulonglong2*)(bsp + bi * 256);
            fma2(acc2[bi], w.x, ae.x);
            fma2(acc2[bi], w.y, ae.y);
        }
    }

    #pragma unroll
    for (int bi = 0; bi < 16; bi++) {
        float2 p = *(float2*)&acc2[bi];
        int b = bh * 16 + bi;
        g_npart[((size_t)blk * 32 + b) * NC2 + j] = p.x + p.y;
    }
}

// ============================================================
// K4c: reduce 64 split-K partials, bias + leaky_relu -> out
// ============================================================
__global__ void k_nred(const float* __restrict__ b_node, float* __restrict__ out) {
    int b = blockIdx.x, j = threadIdx.x;
    float s = 0.f;
    #pragma unroll 8
    for (int sp = 0; sp < 64; sp++)
        s += g_npart[((size_t)sp * 32 + b) * NC2 + j];
    s += b_node[j];
    out[b * NC2 + j] = s > 0.f ? s : 0.01f * s;
}

// ============================================================
extern "C" void kernel_launch(void* const* d_in, const int* in_sizes, int n_in,
                              void* d_out, int out_size) {
    const float* x      = (const float*)d_in[0];
    const float* W_edge = (const float*)d_in[1];
    const float* b_edge = (const float*)d_in[2];
    const float* W1     = (const float*)d_in[3];
    const float* b1     = (const float*)d_in[4];
    const float* W2     = (const float*)d_in[5];
    const float* b2     = (const float*)d_in[6];
    const float* W_node = (const float*)d_in[7];
    const float* b_node = (const float*)d_in[8];
    float* out = (float*)d_out;

    const int smemY = (2 * 32 * 68 + 2 * 32 * 260) * 4;   // 83,968 B
    const int smemE = 2 * EST;                            // 102,400 B
    cudaFuncSetAttribute(k_y, cudaFuncAttributeMaxDynamicSharedMemorySize, smemY);
    cudaFuncSetAttribute(k_e_hmma, cudaFuncAttributeMaxDynamicSharedMemorySize, smemE);

    k_stats <<<Bsz * Rr, 256>>>(x);
    k_y     <<<Bsz * Cc * 2, 256, smemY>>>(W_edge);
    k_e_hmma<<<Bsz * 4, 256, smemE>>>();
    k_reduce<<<Bsz * Rr, 64>>>(b_edge);
    k_att   <<<Bsz, 256>>>(W1, b1, W2, b2, out);
    k_node  <<<64, 256>>>(W_node);
    k_nred  <<<Bsz, 128>>>(b_node, out);
}

// round 11
// speedup vs baseline: 1.5130x; 1.1511x over previous
#include <cuda_runtime.h>
#include <cuda_bf16.h>
#include <math.h>

#define Bsz 32
#define Rr  256
#define Tt  512
#define Cc  16
#define NC1 64
#define NC2 128

// ---- scratch (static __device__ per allocation rules) ----
__device__ __nv_bfloat16 g_zh[67108864];        // [B*C][R][T] bf16 hi of z
__device__ __nv_bfloat16 g_zl[67108864];        // bf16 lo of z
__device__ __nv_bfloat16 g_yh[16777216];        // [B*C][C1][T] bf16 hi of y
__device__ __nv_bfloat16 g_yl[16777216];        // bf16 lo of y
__device__ float g_epart[2097152];              // [4 cg][32 b][256 r][64 o]
__device__ float g_e[524288];                   // [B][R][C1]
__device__ float g_pooled[8192];                // [B][R]
__device__ float g_att[8192];                   // [B][R]
__device__ float g_npart[262144];               // [64 splits][32 b][128 j]

__device__ __forceinline__ void fma2(unsigned long long &d,
                                     unsigned long long a,
                                     unsigned long long b) {
    asm("fma.rn.f32x2 %0, %1, %2, %0;" : "+l"(d) : "l"(a), "l"(b));
}
__device__ __forceinline__ unsigned smem_u32(const void* p) {
    return (unsigned)__cvta_generic_to_shared(p);
}
__device__ __forceinline__ void cp16(unsigned dst, const void* src) {
    asm volatile("cp.async.cg.shared.global [%0], [%1], 16;" :: "r"(dst), "l"(src));
}
#define CP_COMMIT() asm volatile("cp.async.commit_group;")
#define CP_WAIT0()  asm volatile("cp.async.wait_group 0;")
#define CP_WAIT1()  asm volatile("cp.async.wait_group 1;")

// bf16 2-way split of a float pair. hi word: [lo16]=bf16(a), [hi16]=bf16(b).
__device__ __forceinline__ void bf16_split2(float a, float b, unsigned &hi, unsigned &lo) {
    unsigned h;
    asm("cvt.rn.bf16x2.f32 %0, %1, %2;" : "=r"(h) : "f"(b), "f"(a));
    float ha = __uint_as_float(h << 16);
    float hb = __uint_as_float(h & 0xffff0000u);
    unsigned l;
    asm("cvt.rn.bf16x2.f32 %0, %1, %2;" : "=r"(l) : "f"(b - hb), "f"(a - ha));
    hi = h; lo = l;
}

// ---- warp-level tensor core (sm_80+ baseline; works on compute_103) ----
#define LDSM4(r, addr) \
    asm volatile("ldmatrix.sync.aligned.m8n8.x4.shared.b16 {%0,%1,%2,%3}, [%4];" \
        : "=r"((r)[0]), "=r"((r)[1]), "=r"((r)[2]), "=r"((r)[3]) : "r"(addr))

#define LDSM4T(r, addr) \
    asm volatile("ldmatrix.sync.aligned.m8n8.x4.trans.shared.b16 {%0,%1,%2,%3}, [%4];" \
        : "=r"((r)[0]), "=r"((r)[1]), "=r"((r)[2]), "=r"((r)[3]) : "r"(addr))

#define MMA16816(d, a, bp) \
    asm volatile("mma.sync.aligned.m16n8k16.row.col.f32.bf16.bf16.f32 " \
        "{%0,%1,%2,%3}, {%4,%5,%6,%7}, {%8,%9}, {%0,%1,%2,%3};" \
        : "+f"((d)[0]), "+f"((d)[1]), "+f"((d)[2]), "+f"((d)[3]) \
        : "r"((a)[0]), "r"((a)[1]), "r"((a)[2]), "r"((a)[3]), \
          "r"((bp)[0]), "r"((bp)[1]))

// ============================================================
// K1: per (b,r): stats + write z bf16 hi/lo [bc][r][t]
// ============================================================
__global__ void k_stats(const float* __restrict__ x) {
    int br = blockIdx.x;                 // b*R + r
    int b = br >> 8, r = br & 255;
    __shared__ __align__(16) float sx[Cc * 513];
    __shared__ float red[256];
    __shared__ float s_mean[Cc], s_inv[Cc];
    const float* xp = x + (size_t)br * (Tt * Cc);
    int tid = threadIdx.x;

    #pragma unroll
    for (int i = 0; i < 8; i++) {
        int idx4 = tid + i * 256;
        int t = idx4 >> 2;
        int c0 = (idx4 & 3) * 4;
        float4 v = *(const float4*)(xp + idx4 * 4);
        sx[(c0 + 0) * 513 + t] = v.x;
        sx[(c0 + 1) * 513 + t] = v.y;
        sx[(c0 + 2) * 513 + t] = v.z;
        sx[(c0 + 3) * 513 + t] = v.w;
    }
    __syncthreads();

    int c = tid & 15, seg = tid >> 4;
    float p = 0.f;
    #pragma unroll
    for (int u = 0; u < 32; u++) p += sx[c * 513 + seg * 32 + u];
    red[seg * 16 + c] = p;
    __syncthreads();
    if (tid < 16) {
        float s = 0.f;
        #pragma unroll
        for (int sg = 0; sg < 16; sg++) s += red[sg * 16 + tid];
        s_mean[tid] = s * (1.0f / Tt);
    }
    __syncthreads();

    float mc = s_mean[c];
    p = 0.f;
    #pragma unroll
    for (int u = 0; u < 32; u++) {
        float d = sx[c * 513 + seg * 32 + u] - mc;
        p += d * d;
    }
    red[seg * 16 + c] = p;
    __syncthreads();
    if (tid < 16) {
        float s = 0.f;
        #pragma unroll
        for (int sg = 0; sg < 16; sg++) s += red[sg * 16 + tid];
        s_inv[tid] = rsqrtf(s);
    }
    __syncthreads();

    int cw = tid >> 4;
    float m = s_mean[cw], inv = s_inv[cw];
    size_t zoff = (((size_t)b * Cc + cw) * Rr + r) * Tt;
    __nv_bfloat16* zh = g_zh + zoff;
    __nv_bfloat16* zl = g_zl + zoff;
    int q = tid & 15;
    #pragma unroll
    for (int j = 0; j < 16; j++) {
        int t = q * 2 + j * 32;
        float z0 = (sx[cw * 513 + t] - m) * inv;
        float z1 = (sx[cw * 513 + t + 1] - m) * inv;
        unsigned hw, lw;
        bf16_split2(z0, z1, hw, lw);
        *(unsigned*)(zh + t) = hw;
        *(unsigned*)(zl + t) = lw;
    }
}

// ============================================================
// K2a (HMMA): y[bc][o][t] = sum_r W_edge[o][c][r] * z[bc][r][t]
// grid 1024 = bc*2 + ttile; block 256 (8 warps).
// A = W bf16 hi/lo [64 o][256 r] split in prologue, resident in smem,
//     rows padded to 264 (528B -> conflict-free LDSM).
// B = z [r][t] row-major-K -> ldmatrix.trans gives b-frag.
// Warp tile 32o x 64t; 3 chains (hh, hl, lh); 2-stage cp.async on z.
// smem: W 2x[64][264] + Z 2buf x 2(h/l) x [32][264] = 135,168 B
// ============================================================
#define YWS 264

__global__ __launch_bounds__(256, 1) void k_y_hmma(const float* __restrict__ W_edge) {
    extern __shared__ __align__(16) __nv_bfloat16 ysm[];
    __nv_bfloat16* Wh = ysm;                       // [64][264]
    __nv_bfloat16* Wl = Wh + 64 * YWS;
    __nv_bfloat16* Zb = Wl + 64 * YWS;             // [2 buf][2 h/l][32][264]
    int tid = threadIdx.x;
    int wid = tid >> 5, lane = tid & 31;
    int bc = blockIdx.x >> 1, tt = blockIdx.x & 1;
    int tbase = tt * 256;
    int c = bc & 15;
    int mw = wid & 1, nw = wid >> 1;

    // ---- prologue: split W[:,c,:] fp32 -> bf16 hi/lo in smem ----
    {
        const float* wrow = W_edge + (size_t)(tid >> 2) * (Cc * Rr) + (size_t)c * Rr
                          + (tid & 3) * 64;
        int wo = tid >> 2, wrs = (tid & 3) * 64;
        #pragma unroll
        for (int j = 0; j < 32; j++) {
            float2 v = *(const float2*)(wrow + j * 2);
            unsigned h, l;
            bf16_split2(v.x, v.y, h, l);
            *(unsigned*)(Wh + wo * YWS + wrs + j * 2) = h;
            *(unsigned*)(Wl + wo * YWS + wrs + j * 2) = l;
        }
    }

    const __nv_bfloat16* zh0 = g_zh + (size_t)bc * Rr * Tt + tbase;
    const __nv_bfloat16* zl0 = g_zl + (size_t)bc * Rr * Tt + tbase;

    auto zfill = [&](int kb, int buf) {
        unsigned dhu = smem_u32(Zb + buf * (2 * 32 * YWS));
        unsigned dlu = dhu + (unsigned)(32 * YWS) * 2;
        #pragma unroll
        for (int i = 0; i < 4; i++) {
            int idx = tid + i * 256;        // 0..1023
            int row = idx >> 5, seg = idx & 31;
            unsigned doff = (unsigned)(row * YWS + seg * 8) * 2;
            size_t soff = (size_t)(kb * 32 + row) * Tt + seg * 8;
            cp16(dhu + doff, zh0 + soff);
            cp16(dlu + doff, zl0 + soff);
        }
        CP_COMMIT();
    };

    float acc[2][8][4];
    #pragma unroll
    for (int mt = 0; mt < 2; mt++)
        #pragma unroll
        for (int nt = 0; nt < 8; nt++)
            #pragma unroll
            for (int u = 0; u < 4; u++) acc[mt][nt][u] = 0.f;

    int matq = lane >> 3, qr = lane & 7;
    // A (non-trans): rows = o, k contiguous
    unsigned aoff = (unsigned)(((matq & 1) * 8 + qr) * YWS + (matq >> 1) * 8) * 2;
    unsigned awh = smem_u32(Wh + (mw * 32) * YWS) + aoff;
    unsigned awl = smem_u32(Wl + (mw * 32) * YWS) + aoff;
    // B (trans): rows = k, t contiguous
    unsigned boff = (unsigned)(((matq & 1) * 8 + qr) * YWS + nw * 64 + (matq >> 1) * 8) * 2;

    zfill(0, 0);
    for (int kb = 0; kb < 8; kb++) {
        __syncthreads();
        if (kb + 1 < 8) { zfill(kb + 1, (kb + 1) & 1); CP_WAIT1(); }
        else CP_WAIT0();
        __syncthreads();

        unsigned zh_b = smem_u32(Zb + (kb & 1) * (2 * 32 * YWS)) + boff;
        unsigned zl_b = zh_b + (unsigned)(32 * YWS) * 2;
        #pragma unroll
        for (int k0 = 0; k0 < 2; k0++) {
            unsigned akoff = (unsigned)(kb * 32 + k0 * 16) * 2;
            unsigned ah[2][4], al[2][4];
            LDSM4(ah[0], awh + akoff);
            LDSM4(ah[1], awh + (unsigned)(16 * YWS) * 2 + akoff);
            LDSM4(al[0], awl + akoff);
            LDSM4(al[1], awl + (unsigned)(16 * YWS) * 2 + akoff);
            unsigned zrow = (unsigned)(k0 * 16 * YWS) * 2;
            #pragma unroll
            for (int i = 0; i < 4; i++) {
                unsigned bh4[4], bl4[4];
                LDSM4T(bh4, zh_b + zrow + (unsigned)(i * 16) * 2);
                LDSM4T(bl4, zl_b + zrow + (unsigned)(i * 16) * 2);
                #pragma unroll
                for (int mt = 0; mt < 2; mt++) {
                    #pragma unroll
                    for (int h = 0; h < 2; h++) {
                        int nt = i * 2 + h;
                        MMA16816(acc[mt][nt], ah[mt], &bh4[h * 2]);
                        MMA16816(acc[mt][nt], ah[mt], &bl4[h * 2]);
                        MMA16816(acc[mt][nt], al[mt], &bh4[h * 2]);
                    }
                }
            }
        }
    }

    // ---- epilogue: split y to bf16 hi/lo, store [bc][o][t] ----
    __nv_bfloat16* yhb = g_yh + (size_t)bc * (NC1 * Tt) + tbase;
    __nv_bfloat16* ylb = g_yl + (size_t)bc * (NC1 * Tt) + tbase;
    int g = lane >> 2, tq = lane & 3;
    #pragma unroll
    for (int mt = 0; mt < 2; mt++) {
        #pragma unroll
        for (int nt = 0; nt < 8; nt++) {
            int o = mw * 32 + mt * 16 + g;
            int t = nw * 64 + nt * 8 + tq * 2;
            unsigned h0, l0, h1, l1;
            bf16_split2(acc[mt][nt][0], acc[mt][nt][1], h0, l0);
            bf16_split2(acc[mt][nt][2], acc[mt][nt][3], h1, l1);
            *(unsigned*)(yhb + (size_t)o * Tt + t) = h0;
            *(unsigned*)(ylb + (size_t)o * Tt + t) = l0;
            *(unsigned*)(yhb + (size_t)(o + 8) * Tt + t) = h1;
            *(unsigned*)(ylb + (size_t)(o + 8) * Tt + t) = l1;
        }
    }
}

// ============================================================
// K2b (HMMA): epart[cq][b][r][o] = sum_{c in cq-group} sum_t z·y
// grid 128 = b*4 + cq (4 c's each); block 256 (8 warps).  (unchanged R10)
// ============================================================
#define AH_OFF 0
#define AL_OFF 20480
#define BH_OFF 40960
#define BL_OFF 46080
#define EST    51200

__global__ __launch_bounds__(256, 1) void k_e_hmma() {
    extern __shared__ __align__(16) char esm[];
    unsigned base = smem_u32(esm);
    int tid = threadIdx.x;
    int wid = tid >> 5, lane = tid & 31;
    int b = blockIdx.x >> 2, cq = blockIdx.x & 3;

    const __nv_bfloat16* zh0 = g_zh + (size_t)(b * Cc + cq * 4) * Rr * Tt;
    const __nv_bfloat16* zl0 = g_zl + (size_t)(b * Cc + cq * 4) * Rr * Tt;
    const __nv_bfloat16* yh0 = g_yh + (size_t)(b * Cc + cq * 4) * NC1 * Tt;
    const __nv_bfloat16* yl0 = g_yl + (size_t)(b * Cc + cq * 4) * NC1 * Tt;

    int brow = tid & 63, bj = tid >> 6;

    auto fill = [&](int ch, unsigned stage) {
        int ci = ch >> 4, tcn = ch & 15;
        const __nv_bfloat16* zh = zh0 + (size_t)ci * Rr * Tt + tcn * 32;
        const __nv_bfloat16* zl = zl0 + (size_t)ci * Rr * Tt + tcn * 32;
        const __nv_bfloat16* yh = yh0 + (size_t)ci * NC1 * Tt + tcn * 32;
        const __nv_bfloat16* yl = yl0 + (size_t)ci * NC1 * Tt + tcn * 32;
        int r = tid;
        #pragma unroll
        for (int j = 0; j < 4; j++) {
            cp16(stage + AH_OFF + (unsigned)(r * 80 + j * 16), zh + (size_t)r * Tt + j * 8);
            cp16(stage + AL_OFF + (unsigned)(r * 80 + j * 16), zl + (size_t)r * Tt + j * 8);
        }
        cp16(stage + BH_OFF + (unsigned)(brow * 80 + bj * 16), yh + (size_t)brow * Tt + bj * 8);
        cp16(stage + BL_OFF + (unsigned)(brow * 80 + bj * 16), yl + (size_t)brow * Tt + bj * 8);
        CP_COMMIT();
    };

    float acc[2][8][4];
    #pragma unroll
    for (int mt = 0; mt < 2; mt++)
        #pragma unroll
        for (int nt = 0; nt < 8; nt++)
            #pragma unroll
            for (int u = 0; u < 4; u++) acc[mt][nt][u] = 0.f;

    int matq = lane >> 3, qr = lane & 7;
    unsigned a_row = (unsigned)(((matq & 1) * 8 + qr) * 80 + (matq >> 1) * 16);
    unsigned b_row = (unsigned)((((matq >> 1) * 8 + qr)) * 80 + (matq & 1) * 16);

    fill(0, base);
    for (int ch = 0; ch < 64; ch++) {
        unsigned s = base + (unsigned)(ch & 1) * EST;
        __syncthreads();
        if (ch + 1 < 64) {
            fill(ch + 1, base + (unsigned)((ch + 1) & 1) * EST);
            CP_WAIT1();
        } else {
            CP_WAIT0();
        }
        __syncthreads();

        unsigned Ah = s + AH_OFF + (unsigned)(wid * 32) * 80 + a_row;
        unsigned Al = s + AL_OFF + (unsigned)(wid * 32) * 80 + a_row;
        unsigned Bh = s + BH_OFF + b_row;
        unsigned Bl = s + BL_OFF + b_row;

        #pragma unroll
        for (int k0 = 0; k0 < 2; k0++) {
            unsigned koff = (unsigned)(k0 * 32);
            unsigned ah[2][4], al[2][4];
            LDSM4(ah[0], Ah + koff);
            LDSM4(ah[1], Ah + 16 * 80 + koff);
            LDSM4(al[0], Al + koff);
            LDSM4(al[1], Al + 16 * 80 + koff);
            unsigned bh[4][4], bl[4][4];
            #pragma unroll
            for (int i = 0; i < 4; i++) {
                LDSM4(bh[i], Bh + (unsigned)(i * 16) * 80 + koff);
                LDSM4(bl[i], Bl + (unsigned)(i * 16) * 80 + koff);
            }
            #pragma unroll
            for (int mt = 0; mt < 2; mt++) {
                #pragma unroll
                for (int i = 0; i < 4; i++) {
                    #pragma unroll
                    for (int h = 0; h < 2; h++) {
                        int nt = i * 2 + h;
                        MMA16816(acc[mt][nt], ah[mt], &bh[i][h * 2]);
                        MMA16816(acc[mt][nt], ah[mt], &bl[i][h * 2]);
                        MMA16816(acc[mt][nt], al[mt], &bh[i][h * 2]);
                    }
                }
            }
        }
    }

    int g = lane >> 2, tc = lane & 3;
    float* ep = g_epart + ((size_t)cq * Bsz + b) * Rr * NC1;
    #pragma unroll
    for (int mt = 0; mt < 2; mt++) {
        #pragma unroll
        for (int nt = 0; nt < 8; nt++) {
            int r = wid * 32 + mt * 16 + g;
            int o = nt * 8 + tc * 2;
            *(float2*)(ep + (size_t)r * NC1 + o) = make_float2(acc[mt][nt][0], acc[mt][nt][1]);
            *(float2*)(ep + (size_t)(r + 8) * NC1 + o) = make_float2(acc[mt][nt][2], acc[mt][nt][3]);
        }
    }
}

// ============================================================
// K3: sum 4 split-K partials, bias + leaky_relu -> e; pooled
// ============================================================
__global__ void k_reduce(const float* __restrict__ b_edge) {
    int br = blockIdx.x;                  // b*R + r
    int b = br >> 8, r = br & 255;
    int o = threadIdx.x;                  // 0..63
    float s = 0.f;
    #pragma unroll
    for (int cg = 0; cg < 4; cg++)
        s += g_epart[(((size_t)cg * Bsz + b) * Rr + r) * NC1 + o];
    s += b_edge[o];
    s = (s > 0.f) ? s : 0.01f * s;
    g_e[((size_t)b * Rr + r) * NC1 + o] = s;

    float v = s;
    #pragma unroll
    for (int off = 16; off > 0; off >>= 1) v += __shfl_down_sync(0xffffffffu, v, off);
    __shared__ float w2[2];
    if ((o & 31) == 0) w2[o >> 5] = v;
    __syncthreads();
    if (o == 0) g_pooled[b * Rr + r] = (w2[0] + w2[1]) * (1.0f / 64.0f);
}

// ============================================================
// K4a: per b: MLP attention (parallelized layer-1).
// ============================================================
__global__ void k_att(const float* __restrict__ W1, const float* __restrict__ b1,
                      const float* __restrict__ W2, const float* __restrict__ b2,
                      float* __restrict__ out) {
    __shared__ __align__(16) float s_p[256];
    __shared__ __align__(16) float s_h[64];
    int b = blockIdx.x, tid = threadIdx.x;

    s_p[tid] = g_pooled[b * Rr + tid];
    __syncthreads();
    {
        int hi = tid >> 2, q = tid & 3;
        const float* w = W1 + hi * 256 + q * 64;
        float a = 0.f;
        #pragma unroll
        for (int j = 0; j < 16; j++) {
            float4 wv = *(const float4*)(w + j * 4);
            float4 pv = *(const float4*)(s_p + q * 64 + j * 4);
            a += wv.x * pv.x + wv.y * pv.y + wv.z * pv.z + wv.w * pv.w;
        }
        a += __shfl_xor_sync(0xffffffffu, a, 1);
        a += __shfl_xor_sync(0xffffffffu, a, 2);
        if (q == 0) {
            a += b1[hi];
            s_h[hi] = a > 0.f ? a : 0.f;
        }
    }
    __syncthreads();
    {
        float a = b2[tid];
        const float* w = W2 + tid * 64;
        #pragma unroll
        for (int j = 0; j < 16; j++) {
            float4 wv = *(const float4*)(w + j * 4);
            float4 hv = *(const float4*)(s_h + j * 4);
            a += wv.x * hv.x + wv.y * hv.y + wv.z * hv.z + wv.w * hv.w;
        }
        float att = 1.0f / (1.0f + expf(-a));
        g_att[b * Rr + tid] = att;
        out[Bsz * NC2 + b * Rr + tid] = att;
    }
}

// ============================================================
// K4b: NodeConv split-K. 64 blocks, each owns 4 r's.
// ============================================================
__global__ __launch_bounds__(256) void k_node(const float* __restrict__ W_node) {
    __shared__ __align__(16) float sae[32 * 256];       // [b][o][rr]
    __shared__ float s_att[128];
    int blk = blockIdx.x;
    int r0 = blk * 4;
    int tid = threadIdx.x;

    if (tid < 128) {
        int b = tid >> 2, rr = tid & 3;
        s_att[tid] = g_att[b * Rr + r0 + rr];
    }
    __syncthreads();

    #pragma unroll
    for (int i = 0; i < 8; i++) {
        int idx4 = tid + i * 256;
        int b = idx4 >> 6, rr = (idx4 >> 4) & 3, o4 = idx4 & 15;
        float4 v = *(const float4*)(g_e + ((size_t)(b * Rr) + r0 + rr) * NC1 + o4 * 4);
        float a = s_att[b * 4 + rr];
        sae[b * 256 + (o4 * 4 + 0) * 4 + rr] = v.x * a;
        sae[b * 256 + (o4 * 4 + 1) * 4 + rr] = v.y * a;
        sae[b * 256 + (o4 * 4 + 2) * 4 + rr] = v.z * a;
        sae[b * 256 + (o4 * 4 + 3) * 4 + rr] = v.w * a;
    }
    __syncthreads();

    int j = tid >> 1, bh = tid & 1;
    unsigned long long acc2[16];
    #pragma unroll
    for (int i = 0; i < 16; i++) acc2[i] = 0ull;

    const float* wj = W_node + (size_t)j * (NC1 * Rr) + r0;
    #pragma unroll 4
    for (int o = 0; o < 64; o++) {
        ulonglong2 w = *(const ulonglong2*)(wj + o * Rr);
        const float* bsp = sae + bh * 16 * 256 + o * 4;
        #pragma unroll
        for (int bi = 0; bi < 16; bi++) {
            ulonglong2 ae = *(const ulonglong2*)(bsp + bi * 256);
            fma2(acc2[bi], w.x, ae.x);
            fma2(acc2[bi], w.y, ae.y);
        }
    }

    #pragma unroll
    for (int bi = 0; bi < 16; bi++) {
        float2 p = *(float2*)&acc2[bi];
        int b = bh * 16 + bi;
        g_npart[((size_t)blk * 32 + b) * NC2 + j] = p.x + p.y;
    }
}

// ============================================================
// K4c: reduce 64 split-K partials, bias + leaky_relu -> out
// ============================================================
__global__ void k_nred(const float* __restrict__ b_node, float* __restrict__ out) {
    int b = blockIdx.x, j = threadIdx.x;
    float s = 0.f;
    #pragma unroll 8
    for (int sp = 0; sp < 64; sp++)
        s += g_npart[((size_t)sp * 32 + b) * NC2 + j];
    s += b_node[j];
    out[b * NC2 + j] = s > 0.f ? s : 0.01f * s;
}

// ============================================================
extern "C" void kernel_launch(void* const* d_in, const int* in_sizes, int n_in,
                              void* d_out, int out_size) {
    const float* x      = (const float*)d_in[0];
    const float* W_edge = (const float*)d_in[1];
    const float* b_edge = (const float*)d_in[2];
    const float* W1     = (const float*)d_in[3];
    const float* b1     = (const float*)d_in[4];
    const float* W2     = (const float*)d_in[5];
    const float* b2     = (const float*)d_in[6];
    const float* W_node = (const float*)d_in[7];
    const float* b_node = (const float*)d_in[8];
    float* out = (float*)d_out;

    const int smemY = (2 * 64 * YWS + 2 * 2 * 32 * YWS) * 2;   // 135,168 B
    const int smemE = 2 * EST;                                 // 102,400 B
    cudaFuncSetAttribute(k_y_hmma, cudaFuncAttributeMaxDynamicSharedMemorySize, smemY);
    cudaFuncSetAttribute(k_e_hmma, cudaFuncAttributeMaxDynamicSharedMemorySize, smemE);

    k_stats <<<Bsz * Rr, 256>>>(x);
    k_y_hmma<<<Bsz * Cc * 2, 256, smemY>>>(W_edge);
    k_e_hmma<<<Bsz * 4, 256, smemE>>>();
    k_reduce<<<Bsz * Rr, 64>>>(b_edge);
    k_att   <<<Bsz, 256>>>(W1, b1, W2, b2, out);
    k_node  <<<64, 256>>>(W_node);
    k_nred  <<<Bsz, 128>>>(b_node, out);
}

// round 12
// speedup vs baseline: 1.6111x; 1.0649x over previous
#include <cuda_runtime.h>
#include <cuda_bf16.h>
#include <math.h>

#define Bsz 32
#define Rr  256
#define Tt  512
#define Cc  16
#define NC1 64
#define NC2 128

// ---- scratch (static __device__ per allocation rules) ----
__device__ __nv_bfloat16 g_zh[67108864];        // [B*C][R][T] bf16 hi of z
__device__ __nv_bfloat16 g_zl[67108864];        // bf16 lo of z
__device__ float g_epart[8388608];              // [16 c][32 b][256 r][64 o]
__device__ float g_e[524288];                   // [B][R][C1]
__device__ float g_pooled[8192];                // [B][R]
__device__ float g_att[8192];                   // [B][R]
__device__ float g_npart[262144];               // [64 splits][32 b][128 j]

__device__ __forceinline__ void fma2(unsigned long long &d,
                                     unsigned long long a,
                                     unsigned long long b) {
    asm("fma.rn.f32x2 %0, %1, %2, %0;" : "+l"(d) : "l"(a), "l"(b));
}
__device__ __forceinline__ unsigned smem_u32(const void* p) {
    return (unsigned)__cvta_generic_to_shared(p);
}
__device__ __forceinline__ void cp16(unsigned dst, const void* src) {
    asm volatile("cp.async.cg.shared.global [%0], [%1], 16;" :: "r"(dst), "l"(src));
}
#define CP_COMMIT() asm volatile("cp.async.commit_group;")
#define CP_WAIT0()  asm volatile("cp.async.wait_group 0;")
#define CP_WAIT1()  asm volatile("cp.async.wait_group 1;")

// bf16 2-way split of a float pair. hi word: [lo16]=bf16(a), [hi16]=bf16(b).
__device__ __forceinline__ void bf16_split2(float a, float b, unsigned &hi, unsigned &lo) {
    unsigned h;
    asm("cvt.rn.bf16x2.f32 %0, %1, %2;" : "=r"(h) : "f"(b), "f"(a));
    float ha = __uint_as_float(h << 16);
    float hb = __uint_as_float(h & 0xffff0000u);
    unsigned l;
    asm("cvt.rn.bf16x2.f32 %0, %1, %2;" : "=r"(l) : "f"(b - hb), "f"(a - ha));
    hi = h; lo = l;
}

// ---- warp-level tensor core (sm_80+ baseline; works on compute_103) ----
#define LDSM4(r, addr) \
    asm volatile("ldmatrix.sync.aligned.m8n8.x4.shared.b16 {%0,%1,%2,%3}, [%4];" \
        : "=r"((r)[0]), "=r"((r)[1]), "=r"((r)[2]), "=r"((r)[3]) : "r"(addr))

#define LDSM4T(r, addr) \
    asm volatile("ldmatrix.sync.aligned.m8n8.x4.trans.shared.b16 {%0,%1,%2,%3}, [%4];" \
        : "=r"((r)[0]), "=r"((r)[1]), "=r"((r)[2]), "=r"((r)[3]) : "r"(addr))

#define MMA16816(d, a, bp) \
    asm volatile("mma.sync.aligned.m16n8k16.row.col.f32.bf16.bf16.f32 " \
        "{%0,%1,%2,%3}, {%4,%5,%6,%7}, {%8,%9}, {%0,%1,%2,%3};" \
        : "+f"((d)[0]), "+f"((d)[1]), "+f"((d)[2]), "+f"((d)[3]) \
        : "r"((a)[0]), "r"((a)[1]), "r"((a)[2]), "r"((a)[3]), \
          "r"((bp)[0]), "r"((bp)[1]))

// ============================================================
// K1: per (b,r): stats + write z bf16 hi/lo [bc][r][t]
// ============================================================
__global__ void k_stats(const float* __restrict__ x) {
    int br = blockIdx.x;                 // b*R + r
    int b = br >> 8, r = br & 255;
    __shared__ __align__(16) float sx[Cc * 513];
    __shared__ float red[256];
    __shared__ float s_mean[Cc], s_inv[Cc];
    const float* xp = x + (size_t)br * (Tt * Cc);
    int tid = threadIdx.x;

    #pragma unroll
    for (int i = 0; i < 8; i++) {
        int idx4 = tid + i * 256;
        int t = idx4 >> 2;
        int c0 = (idx4 & 3) * 4;
        float4 v = *(const float4*)(xp + idx4 * 4);
        sx[(c0 + 0) * 513 + t] = v.x;
        sx[(c0 + 1) * 513 + t] = v.y;
        sx[(c0 + 2) * 513 + t] = v.z;
        sx[(c0 + 3) * 513 + t] = v.w;
    }
    __syncthreads();

    int c = tid & 15, seg = tid >> 4;
    float p = 0.f;
    #pragma unroll
    for (int u = 0; u < 32; u++) p += sx[c * 513 + seg * 32 + u];
    red[seg * 16 + c] = p;
    __syncthreads();
    if (tid < 16) {
        float s = 0.f;
        #pragma unroll
        for (int sg = 0; sg < 16; sg++) s += red[sg * 16 + tid];
        s_mean[tid] = s * (1.0f / Tt);
    }
    __syncthreads();

    float mc = s_mean[c];
    p = 0.f;
    #pragma unroll
    for (int u = 0; u < 32; u++) {
        float d = sx[c * 513 + seg * 32 + u] - mc;
        p += d * d;
    }
    red[seg * 16 + c] = p;
    __syncthreads();
    if (tid < 16) {
        float s = 0.f;
        #pragma unroll
        for (int sg = 0; sg < 16; sg++) s += red[sg * 16 + tid];
        s_inv[tid] = rsqrtf(s);
    }
    __syncthreads();

    int cw = tid >> 4;
    float m = s_mean[cw], inv = s_inv[cw];
    size_t zoff = (((size_t)b * Cc + cw) * Rr + r) * Tt;
    __nv_bfloat16* zh = g_zh + zoff;
    __nv_bfloat16* zl = g_zl + zoff;
    int q = tid & 15;
    #pragma unroll
    for (int j = 0; j < 8; j++) {
        int t = q * 4 + j * 64;
        float z0 = (sx[cw * 513 + t + 0] - m) * inv;
        float z1 = (sx[cw * 513 + t + 1] - m) * inv;
        float z2 = (sx[cw * 513 + t + 2] - m) * inv;
        float z3 = (sx[cw * 513 + t + 3] - m) * inv;
        unsigned h0, l0, h1, l1;
        bf16_split2(z0, z1, h0, l0);
        bf16_split2(z2, z3, h1, l1);
        uint2 hv; hv.x = h0; hv.y = h1;
        uint2 lv; lv.x = l0; lv.y = l1;
        *(uint2*)(zh + t) = hv;
        *(uint2*)(zl + t) = lv;
    }
}

// ============================================================
// K2 (fused HMMA): per (b,c) CTA.
//  Phase 1 (per 256-t chunk): y[64][256] = W[64][256r] * z[256r][256t]
//     A=W resident smem (264-pad), B=z trans-LDSM; y -> SMEM (h/l split).
//  Phase 2 (per chunk): epart[r][o] += z[r][t] * y[o][t]
//     A=z staged (80B rows), B=y from smem (528B rows); acc persists.
//  3 chains (hh, hl, lh) everywhere. 2-stage cp.async in both phases.
// smem map (bytes): Wh 0, Wl 33792, Yh 67584, Yl 101376, Z 135168(+81920)
// ============================================================
#define YWS  264
#define YROW 528
#define FSM_WH 0
#define FSM_WL 33792
#define FSM_YH 67584
#define FSM_YL 101376
#define FSM_Z  135168
#define FSM_TOTAL 217088

__global__ __launch_bounds__(256, 1) void k_fused(const float* __restrict__ W_edge) {
    extern __shared__ __align__(16) char fsm[];
    unsigned base = smem_u32(fsm);
    int tid = threadIdx.x;
    int wid = tid >> 5, lane = tid & 31;
    int bc = blockIdx.x;
    int b = bc >> 4, c = bc & 15;
    int mw = wid & 1, nw = wid >> 1;

    // ---- prologue: split W[:,c,:] fp32 -> bf16 hi/lo in smem ----
    {
        __nv_bfloat16* Wh = (__nv_bfloat16*)(fsm + FSM_WH);
        __nv_bfloat16* Wl = (__nv_bfloat16*)(fsm + FSM_WL);
        int wo = tid >> 2, wrs = (tid & 3) * 64;
        const float* wrow = W_edge + (size_t)wo * (Cc * Rr) + (size_t)c * Rr + wrs;
        #pragma unroll
        for (int j = 0; j < 32; j++) {
            float2 v = *(const float2*)(wrow + j * 2);
            unsigned h, l;
            bf16_split2(v.x, v.y, h, l);
            *(unsigned*)(Wh + wo * YWS + wrs + j * 2) = h;
            *(unsigned*)(Wl + wo * YWS + wrs + j * 2) = l;
        }
    }

    const __nv_bfloat16* zh0 = g_zh + (size_t)bc * Rr * Tt;
    const __nv_bfloat16* zl0 = g_zl + (size_t)bc * Rr * Tt;

    int matq = lane >> 3, qr = lane & 7;

    // phase-1 addressing
    unsigned p1_aoff = (unsigned)(((matq & 1) * 8 + qr) * YROW + (matq >> 1) * 16);
    unsigned awh = base + FSM_WH + (unsigned)(mw * 32) * YROW + p1_aoff;
    unsigned awl = base + FSM_WL + (unsigned)(mw * 32) * YROW + p1_aoff;
    unsigned p1_boff = (unsigned)(((matq & 1) * 8 + qr) * YROW + (nw * 64 + (matq >> 1) * 8) * 2);
    // phase-2 addressing
    unsigned p2_arow = (unsigned)(((matq & 1) * 8 + qr) * 80 + (matq >> 1) * 16);
    unsigned p2_brow = (unsigned)(((matq >> 1) * 8 + qr) * YROW + (matq & 1) * 16);

    float acc2[2][8][4];
    #pragma unroll
    for (int mt = 0; mt < 2; mt++)
        #pragma unroll
        for (int nt = 0; nt < 8; nt++)
            #pragma unroll
            for (int u = 0; u < 4; u++) acc2[mt][nt][u] = 0.f;

    for (int tc = 0; tc < 2; tc++) {
        int tbase = tc * 256;

        // ================= PHASE 1: y = W * z =================
        // zfill1 into [buf][h/l][32 r][264 t]
        auto zfill1 = [&](int kb, int buf) {
            unsigned dh = base + FSM_Z + (unsigned)buf * 33792u;
            unsigned dl = dh + 16896u;
            #pragma unroll
            for (int i = 0; i < 4; i++) {
                int idx = tid + i * 256;
                int row = idx >> 5, seg = idx & 31;
                unsigned doff = (unsigned)(row * YWS + seg * 8) * 2;
                size_t soff = (size_t)(kb * 32 + row) * Tt + tbase + seg * 8;
                cp16(dh + doff, zh0 + soff);
                cp16(dl + doff, zl0 + soff);
            }
            CP_COMMIT();
        };

        float acc1[2][8][4];
        #pragma unroll
        for (int mt = 0; mt < 2; mt++)
            #pragma unroll
            for (int nt = 0; nt < 8; nt++)
                #pragma unroll
                for (int u = 0; u < 4; u++) acc1[mt][nt][u] = 0.f;

        zfill1(0, 0);
        for (int kb = 0; kb < 8; kb++) {
            __syncthreads();
            if (kb + 1 < 8) { zfill1(kb + 1, (kb + 1) & 1); CP_WAIT1(); }
            else CP_WAIT0();
            __syncthreads();

            unsigned zh_b = base + FSM_Z + (unsigned)(kb & 1) * 33792u + p1_boff;
            unsigned zl_b = zh_b + 16896u;
            #pragma unroll
            for (int k0 = 0; k0 < 2; k0++) {
                unsigned akoff = (unsigned)(kb * 32 + k0 * 16) * 2;
                unsigned ah[2][4], al[2][4];
                LDSM4(ah[0], awh + akoff);
                LDSM4(ah[1], awh + (unsigned)(16 * YROW) + akoff);
                LDSM4(al[0], awl + akoff);
                LDSM4(al[1], awl + (unsigned)(16 * YROW) + akoff);
                unsigned zrow = (unsigned)(k0 * 16) * YROW;
                #pragma unroll
                for (int i = 0; i < 4; i++) {
                    unsigned bh4[4], bl4[4];
                    LDSM4T(bh4, zh_b + zrow + (unsigned)(i * 16) * 2);
                    LDSM4T(bl4, zl_b + zrow + (unsigned)(i * 16) * 2);
                    #pragma unroll
                    for (int mt = 0; mt < 2; mt++) {
                        #pragma unroll
                        for (int h = 0; h < 2; h++) {
                            int nt = i * 2 + h;
                            MMA16816(acc1[mt][nt], ah[mt], &bh4[h * 2]);
                            MMA16816(acc1[mt][nt], ah[mt], &bl4[h * 2]);
                            MMA16816(acc1[mt][nt], al[mt], &bh4[h * 2]);
                        }
                    }
                }
            }
        }

        // write y (bf16 h/l split) into smem [o][264]
        {
            int g = lane >> 2, tq = lane & 3;
            #pragma unroll
            for (int mt = 0; mt < 2; mt++) {
                #pragma unroll
                for (int nt = 0; nt < 8; nt++) {
                    int o = mw * 32 + mt * 16 + g;
                    int t = nw * 64 + nt * 8 + tq * 2;
                    unsigned h0, l0, h1, l1;
                    bf16_split2(acc1[mt][nt][0], acc1[mt][nt][1], h0, l0);
                    bf16_split2(acc1[mt][nt][2], acc1[mt][nt][3], h1, l1);
                    *(unsigned*)(fsm + FSM_YH + o * YROW + t * 2) = h0;
                    *(unsigned*)(fsm + FSM_YL + o * YROW + t * 2) = l0;
                    *(unsigned*)(fsm + FSM_YH + (o + 8) * YROW + t * 2) = h1;
                    *(unsigned*)(fsm + FSM_YL + (o + 8) * YROW + t * 2) = l1;
                }
            }
        }
        __syncthreads();

        // ================= PHASE 2: epart += z * y^T =================
        auto zfill2 = [&](int ch, int buf) {
            unsigned dh = base + FSM_Z + (unsigned)buf * 40960u;
            unsigned dl = dh + 20480u;
            int r = tid;
            size_t soff = (size_t)r * Tt + tbase + ch * 32;
            #pragma unroll
            for (int j = 0; j < 4; j++) {
                cp16(dh + (unsigned)(r * 80 + j * 16), zh0 + soff + j * 8);
                cp16(dl + (unsigned)(r * 80 + j * 16), zl0 + soff + j * 8);
            }
            CP_COMMIT();
        };

        zfill2(0, 0);
        for (int ch = 0; ch < 8; ch++) {
            __syncthreads();
            if (ch + 1 < 8) { zfill2(ch + 1, (ch + 1) & 1); CP_WAIT1(); }
            else CP_WAIT0();
            __syncthreads();

            unsigned Ah = base + FSM_Z + (unsigned)(ch & 1) * 40960u
                        + (unsigned)(wid * 32) * 80 + p2_arow;
            unsigned Al = Ah + 20480u;
            unsigned Bh = base + FSM_YH + p2_brow + (unsigned)(ch * 64);
            unsigned Bl = base + FSM_YL + p2_brow + (unsigned)(ch * 64);

            #pragma unroll
            for (int k0 = 0; k0 < 2; k0++) {
                unsigned koff = (unsigned)(k0 * 32);
                unsigned ah[2][4], al[2][4];
                LDSM4(ah[0], Ah + koff);
                LDSM4(ah[1], Ah + 16 * 80 + koff);
                LDSM4(al[0], Al + koff);
                LDSM4(al[1], Al + 16 * 80 + koff);
                unsigned bh[4][4], bl[4][4];
                #pragma unroll
                for (int i = 0; i < 4; i++) {
                    LDSM4(bh[i], Bh + (unsigned)(i * 16) * YROW + koff);
                    LDSM4(bl[i], Bl + (unsigned)(i * 16) * YROW + koff);
                }
                #pragma unroll
                for (int mt = 0; mt < 2; mt++) {
                    #pragma unroll
                    for (int i = 0; i < 4; i++) {
                        #pragma unroll
                        for (int h = 0; h < 2; h++) {
                            int nt = i * 2 + h;
                            MMA16816(acc2[mt][nt], ah[mt], &bh[i][h * 2]);
                            MMA16816(acc2[mt][nt], ah[mt], &bl[i][h * 2]);
                            MMA16816(acc2[mt][nt], al[mt], &bh[i][h * 2]);
                        }
                    }
                }
            }
        }
        __syncthreads();
    }

    // epilogue: write split-K partials (16-way over c)
    int g = lane >> 2, tq = lane & 3;
    float* ep = g_epart + ((size_t)c * Bsz + b) * Rr * NC1;
    #pragma unroll
    for (int mt = 0; mt < 2; mt++) {
        #pragma unroll
        for (int nt = 0; nt < 8; nt++) {
            int r = wid * 32 + mt * 16 + g;
            int o = nt * 8 + tq * 2;
            *(float2*)(ep + (size_t)r * NC1 + o) = make_float2(acc2[mt][nt][0], acc2[mt][nt][1]);
            *(float2*)(ep + (size_t)(r + 8) * NC1 + o) = make_float2(acc2[mt][nt][2], acc2[mt][nt][3]);
        }
    }
}

// ============================================================
// K3: sum 16 split-K partials, bias + leaky_relu -> e; pooled
// ============================================================
__global__ void k_reduce(const float* __restrict__ b_edge) {
    int br = blockIdx.x;                  // b*R + r
    int b = br >> 8, r = br & 255;
    int o = threadIdx.x;                  // 0..63
    float s = 0.f;
    #pragma unroll
    for (int cg = 0; cg < 16; cg++)
        s += g_epart[(((size_t)cg * Bsz + b) * Rr + r) * NC1 + o];
    s += b_edge[o];
    s = (s > 0.f) ? s : 0.01f * s;
    g_e[((size_t)b * Rr + r) * NC1 + o] = s;

    float v = s;
    #pragma unroll
    for (int off = 16; off > 0; off >>= 1) v += __shfl_down_sync(0xffffffffu, v, off);
    __shared__ float w2[2];
    if ((o & 31) == 0) w2[o >> 5] = v;
    __syncthreads();
    if (o == 0) g_pooled[b * Rr + r] = (w2[0] + w2[1]) * (1.0f / 64.0f);
}

// ============================================================
// K4a: per b: MLP attention (parallelized layer-1).
// ============================================================
__global__ void k_att(const float* __restrict__ W1, const float* __restrict__ b1,
                      const float* __restrict__ W2, const float* __restrict__ b2,
                      float* __restrict__ out) {
    __shared__ __align__(16) float s_p[256];
    __shared__ __align__(16) float s_h[64];
    int b = blockIdx.x, tid = threadIdx.x;

    s_p[tid] = g_pooled[b * Rr + tid];
    __syncthreads();
    {
        int hi = tid >> 2, q = tid & 3;
        const float* w = W1 + hi * 256 + q * 64;
        float a = 0.f;
        #pragma unroll
        for (int j = 0; j < 16; j++) {
            float4 wv = *(const float4*)(w + j * 4);
            float4 pv = *(const float4*)(s_p + q * 64 + j * 4);
            a += wv.x * pv.x + wv.y * pv.y + wv.z * pv.z + wv.w * pv.w;
        }
        a += __shfl_xor_sync(0xffffffffu, a, 1);
        a += __shfl_xor_sync(0xffffffffu, a, 2);
        if (q == 0) {
            a += b1[hi];
            s_h[hi] = a > 0.f ? a : 0.f;
        }
    }
    __syncthreads();
    {
        float a = b2[tid];
        const float* w = W2 + tid * 64;
        #pragma unroll
        for (int j = 0; j < 16; j++) {
            float4 wv = *(const float4*)(w + j * 4);
            float4 hv = *(const float4*)(s_h + j * 4);
            a += wv.x * hv.x + wv.y * hv.y + wv.z * hv.z + wv.w * hv.w;
        }
        float att = 1.0f / (1.0f + expf(-a));
        g_att[b * Rr + tid] = att;
        out[Bsz * NC2 + b * Rr + tid] = att;
    }
}

// ============================================================
// K4b: NodeConv split-K. 64 blocks, each owns 4 r's.
// ============================================================
__global__ __launch_bounds__(256) void k_node(const float* __restrict__ W_node) {
    __shared__ __align__(16) float sae[32 * 256];       // [b][o][rr]
    __shared__ float s_att[128];
    int blk = blockIdx.x;
    int r0 = blk * 4;
    int tid = threadIdx.x;

    if (tid < 128) {
        int b = tid >> 2, rr = tid & 3;
        s_att[tid] = g_att[b * Rr + r0 + rr];
    }
    __syncthreads();

    #pragma unroll
    for (int i = 0; i < 8; i++) {
        int idx4 = tid + i * 256;
        int b = idx4 >> 6, rr = (idx4 >> 4) & 3, o4 = idx4 & 15;
        float4 v = *(const float4*)(g_e + ((size_t)(b * Rr) + r0 + rr) * NC1 + o4 * 4);
        float a = s_att[b * 4 + rr];
        sae[b * 256 + (o4 * 4 + 0) * 4 + rr] = v.x * a;
        sae[b * 256 + (o4 * 4 + 1) * 4 + rr] = v.y * a;
        sae[b * 256 + (o4 * 4 + 2) * 4 + rr] = v.z * a;
        sae[b * 256 + (o4 * 4 + 3) * 4 + rr] = v.w * a;
    }
    __syncthreads();

    int j = tid >> 1, bh = tid & 1;
    unsigned long long acc2[16];
    #pragma unroll
    for (int i = 0; i < 16; i++) acc2[i] = 0ull;

    const float* wj = W_node + (size_t)j * (NC1 * Rr) + r0;
    #pragma unroll 4
    for (int o = 0; o < 64; o++) {
        ulonglong2 w = *(const ulonglong2*)(wj + o * Rr);
        const float* bsp = sae + bh * 16 * 256 + o * 4;
        #pragma unroll
        for (int bi = 0; bi < 16; bi++) {
            ulonglong2 ae = *(const ulonglong2*)(bsp + bi * 256);
            fma2(acc2[bi], w.x, ae.x);
            fma2(acc2[bi], w.y, ae.y);
        }
    }

    #pragma unroll
    for (int bi = 0; bi < 16; bi++) {
        float2 p = *(float2*)&acc2[bi];
        int b = bh * 16 + bi;
        g_npart[((size_t)blk * 32 + b) * NC2 + j] = p.x + p.y;
    }
}

// ============================================================
// K4c: reduce 64 split-K partials, bias + leaky_relu -> out
// ============================================================
__global__ void k_nred(const float* __restrict__ b_node, float* __restrict__ out) {
    int b = blockIdx.x, j = threadIdx.x;
    float s = 0.f;
    #pragma unroll 8
    for (int sp = 0; sp < 64; sp++)
        s += g_npart[((size_t)sp * 32 + b) * NC2 + j];
    s += b_node[j];
    out[b * NC2 + j] = s > 0.f ? s : 0.01f * s;
}

// ============================================================
extern "C" void kernel_launch(void* const* d_in, const int* in_sizes, int n_in,
                              void* d_out, int out_size) {
    const float* x      = (const float*)d_in[0];
    const float* W_edge = (const float*)d_in[1];
    const float* b_edge = (const float*)d_in[2];
    const float* W1     = (const float*)d_in[3];
    const float* b1     = (const float*)d_in[4];
    const float* W2     = (const float*)d_in[5];
    const float* b2     = (const float*)d_in[6];
    const float* W_node = (const float*)d_in[7];
    const float* b_node = (const float*)d_in[8];
    float* out = (float*)d_out;

    cudaFuncSetAttribute(k_fused, cudaFuncAttributeMaxDynamicSharedMemorySize, FSM_TOTAL);

    k_stats <<<Bsz * Rr, 256>>>(x);
    k_fused <<<Bsz * Cc, 256, FSM_TOTAL>>>(W_edge);
    k_reduce<<<Bsz * Rr, 64>>>(b_edge);
    k_att   <<<Bsz, 256>>>(W1, b1, W2, b2, out);
    k_node  <<<64, 256>>>(W_node);
    k_nred  <<<Bsz, 128>>>(b_node, out);
}

// round 14
// speedup vs baseline: 1.6120x; 1.0005x over previous
#include <cuda_runtime.h>
#include <cuda_bf16.h>
#include <math.h>

#define Bsz 32
#define Rr  256
#define Tt  512
#define Cc  16
#define NC1 64
#define NC2 128

// ---- scratch (static __device__ per allocation rules) ----
__device__ __nv_bfloat16 g_zh[67108864];        // [B*C][R][T] bf16 hi of z
__device__ __nv_bfloat16 g_zl[67108864];        // bf16 lo of z
__device__ float g_epart[8388608];              // [16 c][32 b][256 r][64 o]
__device__ float g_e[524288];                   // [B][R][C1]
__device__ float g_pooled[8192];                // [B][R]
__device__ float g_att[8192];                   // [B][R]
__device__ float g_npart[262144];               // [64 splits][32 b][128 j]

__device__ __forceinline__ void fma2(unsigned long long &d,
                                     unsigned long long a,
                                     unsigned long long b) {
    asm("fma.rn.f32x2 %0, %1, %2, %0;" : "+l"(d) : "l"(a), "l"(b));
}
__device__ __forceinline__ unsigned smem_u32(const void* p) {
    return (unsigned)__cvta_generic_to_shared(p);
}
__device__ __forceinline__ void cp16(unsigned dst, const void* src) {
    asm volatile("cp.async.cg.shared.global [%0], [%1], 16;" :: "r"(dst), "l"(src));
}
#define CP_COMMIT() asm volatile("cp.async.commit_group;")
#define CP_WAIT0()  asm volatile("cp.async.wait_group 0;")
#define CP_WAIT1()  asm volatile("cp.async.wait_group 1;")

// bf16 2-way split of a float pair. hi word: [lo16]=bf16(a), [hi16]=bf16(b).
__device__ __forceinline__ void bf16_split2(float a, float b, unsigned &hi, unsigned &lo) {
    unsigned h;
    asm("cvt.rn.bf16x2.f32 %0, %1, %2;" : "=r"(h) : "f"(b), "f"(a));
    float ha = __uint_as_float(h << 16);
    float hb = __uint_as_float(h & 0xffff0000u);
    unsigned l;
    asm("cvt.rn.bf16x2.f32 %0, %1, %2;" : "=r"(l) : "f"(b - hb), "f"(a - ha));
    hi = h; lo = l;
}

// ---- warp-level tensor core (sm_80+ baseline; works on compute_103) ----
#define LDSM4(r, addr) \
    asm volatile("ldmatrix.sync.aligned.m8n8.x4.shared.b16 {%0,%1,%2,%3}, [%4];" \
        : "=r"((r)[0]), "=r"((r)[1]), "=r"((r)[2]), "=r"((r)[3]) : "r"(addr))

#define LDSM4T(r, addr) \
    asm volatile("ldmatrix.sync.aligned.m8n8.x4.trans.shared.b16 {%0,%1,%2,%3}, [%4];" \
        : "=r"((r)[0]), "=r"((r)[1]), "=r"((r)[2]), "=r"((r)[3]) : "r"(addr))

#define MMA16816(d, a, bp) \
    asm volatile("mma.sync.aligned.m16n8k16.row.col.f32.bf16.bf16.f32 " \
        "{%0,%1,%2,%3}, {%4,%5,%6,%7}, {%8,%9}, {%0,%1,%2,%3};" \
        : "+f"((d)[0]), "+f"((d)[1]), "+f"((d)[2]), "+f"((d)[3]) \
        : "r"((a)[0]), "r"((a)[1]), "r"((a)[2]), "r"((a)[3]), \
          "r"((bp)[0]), "r"((bp)[1]))

// ============================================================
// K1: per (b,r): stats + write z bf16 hi/lo [bc][r][t]
// ============================================================
__global__ void k_stats(const float* __restrict__ x) {
    int br = blockIdx.x;                 // b*R + r
    int b = br >> 8, r = br & 255;
    __shared__ __align__(16) float sx[Cc * 513];
    __shared__ float red[256];
    __shared__ float s_mean[Cc], s_inv[Cc];
    const float* xp = x + (size_t)br * (Tt * Cc);
    int tid = threadIdx.x;

    #pragma unroll
    for (int i = 0; i < 8; i++) {
        int idx4 = tid + i * 256;
        int t = idx4 >> 2;
        int c0 = (idx4 & 3) * 4;
        float4 v = *(const float4*)(xp + idx4 * 4);
        sx[(c0 + 0) * 513 + t] = v.x;
        sx[(c0 + 1) * 513 + t] = v.y;
        sx[(c0 + 2) * 513 + t] = v.z;
        sx[(c0 + 3) * 513 + t] = v.w;
    }
    __syncthreads();

    int c = tid & 15, seg = tid >> 4;
    float p = 0.f;
    #pragma unroll
    for (int u = 0; u < 32; u++) p += sx[c * 513 + seg * 32 + u];
    red[seg * 16 + c] = p;
    __syncthreads();
    if (tid < 16) {
        float s = 0.f;
        #pragma unroll
        for (int sg = 0; sg < 16; sg++) s += red[sg * 16 + tid];
        s_mean[tid] = s * (1.0f / Tt);
    }
    __syncthreads();

    float mc = s_mean[c];
    p = 0.f;
    #pragma unroll
    for (int u = 0; u < 32; u++) {
        float d = sx[c * 513 + seg * 32 + u] - mc;
        p += d * d;
    }
    red[seg * 16 + c] = p;
    __syncthreads();
    if (tid < 16) {
        float s = 0.f;
        #pragma unroll
        for (int sg = 0; sg < 16; sg++) s += red[sg * 16 + tid];
        s_inv[tid] = rsqrtf(s);
    }
    __syncthreads();

    int cw = tid >> 4;
    float m = s_mean[cw], inv = s_inv[cw];
    size_t zoff = (((size_t)b * Cc + cw) * Rr + r) * Tt;
    __nv_bfloat16* zh = g_zh + zoff;
    __nv_bfloat16* zl = g_zl + zoff;
    int q = tid & 15;
    #pragma unroll
    for (int j = 0; j < 8; j++) {
        int t = q * 4 + j * 64;
        float z0 = (sx[cw * 513 + t + 0] - m) * inv;
        float z1 = (sx[cw * 513 + t + 1] - m) * inv;
        float z2 = (sx[cw * 513 + t + 2] - m) * inv;
        float z3 = (sx[cw * 513 + t + 3] - m) * inv;
        unsigned h0, l0, h1, l1;
        bf16_split2(z0, z1, h0, l0);
        bf16_split2(z2, z3, h1, l1);
        uint2 hv; hv.x = h0; hv.y = h1;
        uint2 lv; lv.x = l0; lv.y = l1;
        *(uint2*)(zh + t) = hv;
        *(uint2*)(zl + t) = lv;
    }
}

// ============================================================
// K2 (fused HMMA): per (b,c) CTA.  (R12 + chain-major MMA reorder:
//  the 3 accuracy chains issue as separate passes so no back-to-back
//  RAW on the same accumulator -> tensor pipe streams at 2 warps/SMSP.)
// ============================================================
#define YWS  264
#define YROW 528
#define FSM_WH 0
#define FSM_WL 33792
#define FSM_YH 67584
#define FSM_YL 101376
#define FSM_Z  135168
#define FSM_TOTAL 217088

__global__ __launch_bounds__(256, 1) void k_fused(const float* __restrict__ W_edge) {
    extern __shared__ __align__(16) char fsm[];
    unsigned base = smem_u32(fsm);
    int tid = threadIdx.x;
    int wid = tid >> 5, lane = tid & 31;
    int bc = blockIdx.x;
    int b = bc >> 4, c = bc & 15;
    int mw = wid & 1, nw = wid >> 1;

    // ---- prologue: split W[:,c,:] fp32 -> bf16 hi/lo in smem ----
    {
        __nv_bfloat16* Wh = (__nv_bfloat16*)(fsm + FSM_WH);
        __nv_bfloat16* Wl = (__nv_bfloat16*)(fsm + FSM_WL);
        int wo = tid >> 2, wrs = (tid & 3) * 64;
        const float* wrow = W_edge + (size_t)wo * (Cc * Rr) + (size_t)c * Rr + wrs;
        #pragma unroll
        for (int j = 0; j < 32; j++) {
            float2 v = *(const float2*)(wrow + j * 2);
            unsigned h, l;
            bf16_split2(v.x, v.y, h, l);
            *(unsigned*)(Wh + wo * YWS + wrs + j * 2) = h;
            *(unsigned*)(Wl + wo * YWS + wrs + j * 2) = l;
        }
    }

    const __nv_bfloat16* zh0 = g_zh + (size_t)bc * Rr * Tt;
    const __nv_bfloat16* zl0 = g_zl + (size_t)bc * Rr * Tt;

    int matq = lane >> 3, qr = lane & 7;

    unsigned p1_aoff = (unsigned)(((matq & 1) * 8 + qr) * YROW + (matq >> 1) * 16);
    unsigned awh = base + FSM_WH + (unsigned)(mw * 32) * YROW + p1_aoff;
    unsigned awl = base + FSM_WL + (unsigned)(mw * 32) * YROW + p1_aoff;
    unsigned p1_boff = (unsigned)(((matq & 1) * 8 + qr) * YROW + (nw * 64 + (matq >> 1) * 8) * 2);
    unsigned p2_arow = (unsigned)(((matq & 1) * 8 + qr) * 80 + (matq >> 1) * 16);
    unsigned p2_brow = (unsigned)(((matq >> 1) * 8 + qr) * YROW + (matq & 1) * 16);

    float acc2[2][8][4];
    #pragma unroll
    for (int mt = 0; mt < 2; mt++)
        #pragma unroll
        for (int nt = 0; nt < 8; nt++)
            #pragma unroll
            for (int u = 0; u < 4; u++) acc2[mt][nt][u] = 0.f;

    for (int tc = 0; tc < 2; tc++) {
        int tbase = tc * 256;

        // ================= PHASE 1: y = W * z =================
        auto zfill1 = [&](int kb, int buf) {
            unsigned dh = base + FSM_Z + (unsigned)buf * 33792u;
            unsigned dl = dh + 16896u;
            #pragma unroll
            for (int i = 0; i < 4; i++) {
                int idx = tid + i * 256;
                int row = idx >> 5, seg = idx & 31;
                unsigned doff = (unsigned)(row * YWS + seg * 8) * 2;
                size_t soff = (size_t)(kb * 32 + row) * Tt + tbase + seg * 8;
                cp16(dh + doff, zh0 + soff);
                cp16(dl + doff, zl0 + soff);
            }
            CP_COMMIT();
        };

        float acc1[2][8][4];
        #pragma unroll
        for (int mt = 0; mt < 2; mt++)
            #pragma unroll
            for (int nt = 0; nt < 8; nt++)
                #pragma unroll
                for (int u = 0; u < 4; u++) acc1[mt][nt][u] = 0.f;

        zfill1(0, 0);
        for (int kb = 0; kb < 8; kb++) {
            __syncthreads();
            if (kb + 1 < 8) { zfill1(kb + 1, (kb + 1) & 1); CP_WAIT1(); }
            else CP_WAIT0();
            __syncthreads();

            unsigned zh_b = base + FSM_Z + (unsigned)(kb & 1) * 33792u + p1_boff;
            unsigned zl_b = zh_b + 16896u;
            #pragma unroll
            for (int k0 = 0; k0 < 2; k0++) {
                unsigned akoff = (unsigned)(kb * 32 + k0 * 16) * 2;
                unsigned ah[2][4], al[2][4];
                LDSM4(ah[0], awh + akoff);
                LDSM4(ah[1], awh + (unsigned)(16 * YROW) + akoff);
                LDSM4(al[0], awl + akoff);
                LDSM4(al[1], awl + (unsigned)(16 * YROW) + akoff);
                unsigned zrow = (unsigned)(k0 * 16) * YROW;
                unsigned bh4[4][4], bl4[4][4];
                #pragma unroll
                for (int i = 0; i < 4; i++) {
                    LDSM4T(bh4[i], zh_b + zrow + (unsigned)(i * 16) * 2);
                    LDSM4T(bl4[i], zl_b + zrow + (unsigned)(i * 16) * 2);
                }
                // chain-major: hh pass, hl pass, lh pass (no acc RAW chains)
                #pragma unroll
                for (int mt = 0; mt < 2; mt++)
                    #pragma unroll
                    for (int i = 0; i < 4; i++)
                        #pragma unroll
                        for (int h = 0; h < 2; h++)
                            MMA16816(acc1[mt][i * 2 + h], ah[mt], &bh4[i][h * 2]);
                #pragma unroll
                for (int mt = 0; mt < 2; mt++)
                    #pragma unroll
                    for (int i = 0; i < 4; i++)
                        #pragma unroll
                        for (int h = 0; h < 2; h++)
                            MMA16816(acc1[mt][i * 2 + h], ah[mt], &bl4[i][h * 2]);
                #pragma unroll
                for (int mt = 0; mt < 2; mt++)
                    #pragma unroll
                    for (int i = 0; i < 4; i++)
                        #pragma unroll
                        for (int h = 0; h < 2; h++)
                            MMA16816(acc1[mt][i * 2 + h], al[mt], &bh4[i][h * 2]);
            }
        }

        // write y (bf16 h/l split) into smem [o][264]
        {
            int g = lane >> 2, tq = lane & 3;
            #pragma unroll
            for (int mt = 0; mt < 2; mt++) {
                #pragma unroll
                for (int nt = 0; nt < 8; nt++) {
                    int o = mw * 32 + mt * 16 + g;
                    int t = nw * 64 + nt * 8 + tq * 2;
                    unsigned h0, l0, h1, l1;
                    bf16_split2(acc1[mt][nt][0], acc1[mt][nt][1], h0, l0);
                    bf16_split2(acc1[mt][nt][2], acc1[mt][nt][3], h1, l1);
                    *(unsigned*)(fsm + FSM_YH + o * YROW + t * 2) = h0;
                    *(unsigned*)(fsm + FSM_YL + o * YROW + t * 2) = l0;
                    *(unsigned*)(fsm + FSM_YH + (o + 8) * YROW + t * 2) = h1;
                    *(unsigned*)(fsm + FSM_YL + (o + 8) * YROW + t * 2) = l1;
                }
            }
        }
        __syncthreads();

        // ================= PHASE 2: epart += z * y^T =================
        auto zfill2 = [&](int ch, int buf) {
            unsigned dh = base + FSM_Z + (unsigned)buf * 40960u;
            unsigned dl = dh + 20480u;
            int r = tid;
            size_t soff = (size_t)r * Tt + tbase + ch * 32;
            #pragma unroll
            for (int j = 0; j < 4; j++) {
                cp16(dh + (unsigned)(r * 80 + j * 16), zh0 + soff + j * 8);
                cp16(dl + (unsigned)(r * 80 + j * 16), zl0 + soff + j * 8);
            }
            CP_COMMIT();
        };

        zfill2(0, 0);
        for (int ch = 0; ch < 8; ch++) {
            __syncthreads();
            if (ch + 1 < 8) { zfill2(ch + 1, (ch + 1) & 1); CP_WAIT1(); }
            else CP_WAIT0();
            __syncthreads();

            unsigned Ah = base + FSM_Z + (unsigned)(ch & 1) * 40960u
                        + (unsigned)(wid * 32) * 80 + p2_arow;
            unsigned Al = Ah + 20480u;
            unsigned Bh = base + FSM_YH + p2_brow + (unsigned)(ch * 64);
            unsigned Bl = base + FSM_YL + p2_brow + (unsigned)(ch * 64);

            #pragma unroll
            for (int k0 = 0; k0 < 2; k0++) {
                unsigned koff = (unsigned)(k0 * 32);
                unsigned ah[2][4], al[2][4];
                LDSM4(ah[0], Ah + koff);
                LDSM4(ah[1], Ah + 16 * 80 + koff);
                LDSM4(al[0], Al + koff);
                LDSM4(al[1], Al + 16 * 80 + koff);
                unsigned bh[4][4], bl[4][4];
                #pragma unroll
                for (int i = 0; i < 4; i++) {
                    LDSM4(bh[i], Bh + (unsigned)(i * 16) * YROW + koff);
                    LDSM4(bl[i], Bl + (unsigned)(i * 16) * YROW + koff);
                }
                // chain-major passes
                #pragma unroll
                for (int mt = 0; mt < 2; mt++)
                    #pragma unroll
                    for (int i = 0; i < 4; i++)
                        #pragma unroll
                        for (int h = 0; h < 2; h++)
                            MMA16816(acc2[mt][i * 2 + h], ah[mt], &bh[i][h * 2]);
                #pragma unroll
                for (int mt = 0; mt < 2; mt++)
                    #pragma unroll
                    for (int i = 0; i < 4; i++)
                        #pragma unroll
                        for (int h = 0; h < 2; h++)
                            MMA16816(acc2[mt][i * 2 + h], ah[mt], &bl[i][h * 2]);
                #pragma unroll
                for (int mt = 0; mt < 2; mt++)
                    #pragma unroll
                    for (int i = 0; i < 4; i++)
                        #pragma unroll
                        for (int h = 0; h < 2; h++)
                            MMA16816(acc2[mt][i * 2 + h], al[mt], &bh[i][h * 2]);
            }
        }
        __syncthreads();
    }

    // epilogue: write split-K partials (16-way over c)
    int g = lane >> 2, tq = lane & 3;
    float* ep = g_epart + ((size_t)c * Bsz + b) * Rr * NC1;
    #pragma unroll
    for (int mt = 0; mt < 2; mt++) {
        #pragma unroll
        for (int nt = 0; nt < 8; nt++) {
            int r = wid * 32 + mt * 16 + g;
            int o = nt * 8 + tq * 2;
            *(float2*)(ep + (size_t)r * NC1 + o) = make_float2(acc2[mt][nt][0], acc2[mt][nt][1]);
            *(float2*)(ep + (size_t)(r + 8) * NC1 + o) = make_float2(acc2[mt][nt][2], acc2[mt][nt][3]);
        }
    }
}

// ============================================================
// K3: sum 16 split-K partials, bias + leaky_relu -> e; pooled
// ============================================================
__global__ void k_reduce(const float* __restrict__ b_edge) {
    int br = blockIdx.x;                  // b*R + r
    int b = br >> 8, r = br & 255;
    int o = threadIdx.x;                  // 0..63
    float s = 0.f;
    #pragma unroll
    for (int cg = 0; cg < 16; cg++)
        s += g_epart[(((size_t)cg * Bsz + b) * Rr + r) * NC1 + o];
    s += b_edge[o];
    s = (s > 0.f) ? s : 0.01f * s;
    g_e[((size_t)b * Rr + r) * NC1 + o] = s;

    float v = s;
    #pragma unroll
    for (int off = 16; off > 0; off >>= 1) v += __shfl_down_sync(0xffffffffu, v, off);
    __shared__ float w2[2];
    if ((o & 31) == 0) w2[o >> 5] = v;
    __syncthreads();
    if (o == 0) g_pooled[b * Rr + r] = (w2[0] + w2[1]) * (1.0f / 64.0f);
}

// ============================================================
// K4a: per b: MLP attention (parallelized layer-1).
// ============================================================
__global__ void k_att(const float* __restrict__ W1, const float* __restrict__ b1,
                      const float* __restrict__ W2, const float* __restrict__ b2,
                      float* __restrict__ out) {
    __shared__ __align__(16) float s_p[256];
    __shared__ __align__(16) float s_h[64];
    int b = blockIdx.x, tid = threadIdx.x;

    s_p[tid] = g_pooled[b * Rr + tid];
    __syncthreads();
    {
        int hi = tid >> 2, q = tid & 3;
        const float* w = W1 + hi * 256 + q * 64;
        float a = 0.f;
        #pragma unroll
        for (int j = 0; j < 16; j++) {
            float4 wv = *(const float4*)(w + j * 4);
            float4 pv = *(const float4*)(s_p + q * 64 + j * 4);
            a += wv.x * pv.x + wv.y * pv.y + wv.z * pv.z + wv.w * pv.w;
        }
        a += __shfl_xor_sync(0xffffffffu, a, 1);
        a += __shfl_xor_sync(0xffffffffu, a, 2);
        if (q == 0) {
            a += b1[hi];
            s_h[hi] = a > 0.f ? a : 0.f;
        }
    }
    __syncthreads();
    {
        float a = b2[tid];
        const float* w = W2 + tid * 64;
        #pragma unroll
        for (int j = 0; j < 16; j++) {
            float4 wv = *(const float4*)(w + j * 4);
            float4 hv = *(const float4*)(s_h + j * 4);
            a += wv.x * hv.x + wv.y * hv.y + wv.z * hv.z + wv.w * hv.w;
        }
        float att = 1.0f / (1.0f + expf(-a));
        g_att[b * Rr + tid] = att;
        out[Bsz * NC2 + b * Rr + tid] = att;
    }
}

// ============================================================
// K4b: NodeConv split-K. 64 blocks, each owns 4 r's.
// ============================================================
__global__ __launch_bounds__(256) void k_node(const float* __restrict__ W_node) {
    __shared__ __align__(16) float sae[32 * 256];       // [b][o][rr]
    __shared__ float s_att[128];
    int blk = blockIdx.x;
    int r0 = blk * 4;
    int tid = threadIdx.x;

    if (tid < 128) {
        int b = tid >> 2, rr = tid & 3;
        s_att[tid] = g_att[b * Rr + r0 + rr];
    }
    __syncthreads();

    #pragma unroll
    for (int i = 0; i < 8; i++) {
        int idx4 = tid + i * 256;
        int b = idx4 >> 6, rr = (idx4 >> 4) & 3, o4 = idx4 & 15;
        float4 v = *(const float4*)(g_e + ((size_t)(b * Rr) + r0 + rr) * NC1 + o4 * 4);
        float a = s_att[b * 4 + rr];
        sae[b * 256 + (o4 * 4 + 0) * 4 + rr] = v.x * a;
        sae[b * 256 + (o4 * 4 + 1) * 4 + rr] = v.y * a;
        sae[b * 256 + (o4 * 4 + 2) * 4 + rr] = v.z * a;
        sae[b * 256 + (o4 * 4 + 3) * 4 + rr] = v.w * a;
    }
    __syncthreads();

    int j = tid >> 1, bh = tid & 1;
    unsigned long long acc2[16];
    #pragma unroll
    for (int i = 0; i < 16; i++) acc2[i] = 0ull;

    const float* wj = W_node + (size_t)j * (NC1 * Rr) + r0;
    #pragma unroll 4
    for (int o = 0; o < 64; o++) {
        ulonglong2 w = *(const ulonglong2*)(wj + o * Rr);
        const float* bsp = sae + bh * 16 * 256 + o * 4;
        #pragma unroll
        for (int bi = 0; bi < 16; bi++) {
            ulonglong2 ae = *(const ulonglong2*)(bsp + bi * 256);
            fma2(acc2[bi], w.x, ae.x);
            fma2(acc2[bi], w.y, ae.y);
        }
    }

    #pragma unroll
    for (int bi = 0; bi < 16; bi++) {
        float2 p = *(float2*)&acc2[bi];
        int b = bh * 16 + bi;
        g_npart[((size_t)blk * 32 + b) * NC2 + j] = p.x + p.y;
    }
}

// ============================================================
// K4c: reduce 64 split-K partials, bias + leaky_relu -> out
// ============================================================
__global__ void k_nred(const float* __restrict__ b_node, float* __restrict__ out) {
    int b = blockIdx.x, j = threadIdx.x;
    float s = 0.f;
    #pragma unroll 8
    for (int sp = 0; sp < 64; sp++)
        s += g_npart[((size_t)sp * 32 + b) * NC2 + j];
    s += b_node[j];
    out[b * NC2 + j] = s > 0.f ? s : 0.01f * s;
}

// ============================================================
extern "C" void kernel_launch(void* const* d_in, const int* in_sizes, int n_in,
                              void* d_out, int out_size) {
    const float* x      = (const float*)d_in[0];
    const float* W_edge = (const float*)d_in[1];
    const float* b_edge = (const float*)d_in[2];
    const float* W1     = (const float*)d_in[3];
    const float* b1     = (const float*)d_in[4];
    const float* W2     = (const float*)d_in[5];
    const float* b2     = (const float*)d_in[6];
    const float* W_node = (const float*)d_in[7];
    const float* b_node = (const float*)d_in[8];
    float* out = (float*)d_out;

    cudaFuncSetAttribute(k_fused, cudaFuncAttributeMaxDynamicSharedMemorySize, FSM_TOTAL);

    k_stats <<<Bsz * Rr, 256>>>(x);
    k_fused <<<Bsz * Cc, 256, FSM_TOTAL>>>(W_edge);
    k_reduce<<<Bsz * Rr, 64>>>(b_edge);
    k_att   <<<Bsz, 256>>>(W1, b1, W2, b2, out);
    k_node  <<<64, 256>>>(W_node);
    k_nred  <<<Bsz, 128>>>(b_node, out);
}